// round 1
// baseline (speedup 1.0000x reference)
#include <cuda_runtime.h>
#include <cuda_bf16.h>

// SkinningField fused kernel, Round 1 (fp32 baseline).
// One CTA = 128 points. 256 threads.
// smem: activations A[128][129] (in-place per layer), weight buffer W[128][128],
//       xyz tile, tfs, biases.
// GEMM: 16x16 thread grid, 8x8 register micro-tiles (layers 1,2),
//       32x8 grid with 4x8 tiles for the 59(->64)-wide final layer.
// Epilogue: 128 threads, one point each: hierarchical softmax (55 bones),
//       T blend, x_bar, rot_bar, mat_to_quat.

#define TILE 128
#define SA   129            // padded activation stride (conflict-free scalar LDS)
#define H    128
#define NB   55

__device__ __forceinline__ float sigf(float v) {
    return 1.0f / (1.0f + __expf(-v));
}
__device__ __forceinline__ float sp(float v) {   // softplus = logaddexp(v,0)
    return fmaxf(v, 0.0f) + log1pf(__expf(-fabsf(v)));
}
__device__ __forceinline__ void sm3(float a, float b, float c,
                                    float& oa, float& ob, float& oc) {
    float m = fmaxf(a, fmaxf(b, c));
    float ea = __expf(a - m), eb = __expf(b - m), ec = __expf(c - m);
    float inv = 1.0f / (ea + eb + ec);
    oa = ea * inv; ob = eb * inv; oc = ec * inv;
}
__device__ __forceinline__ void sm5(float a, float b, float c, float d, float e,
                                    float& oa, float& ob, float& oc, float& od, float& oe) {
    float m = fmaxf(fmaxf(a, b), fmaxf(fmaxf(c, d), e));
    float ea = __expf(a - m), eb = __expf(b - m), ec = __expf(c - m),
          ed = __expf(d - m), ee = __expf(e - m);
    float inv = 1.0f / (ea + eb + ec + ed + ee);
    oa = ea * inv; ob = eb * inv; oc = ec * inv; od = ed * inv; oe = ee * inv;
}

__global__ void __launch_bounds__(256, 1)
skin_kernel(const float* __restrict__ xyz,  const float* __restrict__ quats,
            const float* __restrict__ tfs,  const float* __restrict__ aabb_min,
            const float* __restrict__ aabb_max,
            const float* __restrict__ W0, const float* __restrict__ b0,
            const float* __restrict__ W1, const float* __restrict__ b1,
            const float* __restrict__ W2, const float* __restrict__ b2,
            const float* __restrict__ W3, const float* __restrict__ b3,
            float* __restrict__ out, int Npts)
{
    extern __shared__ float smem[];
    float* As    = smem;                 // TILE * SA        = 16512
    float* Ws    = As + TILE * SA;       // 128*128          = 16384
    float* xs    = Ws + H * H;           // 128*3            = 384
    float* tfs_s = xs + TILE * 3;        // 55*16            = 880
    float* bbuf  = tfs_s + NB * 16;      // 128
    float* b3s   = bbuf + H;             // 64

    const int tid   = threadIdx.x;
    const int pbase = blockIdx.x * TILE;

    // ---- stage small inputs ----
    for (int i = tid; i < NB * 16; i += 256) tfs_s[i] = tfs[i];
    for (int i = tid; i < TILE * 3; i += 256) xs[i] = xyz[(size_t)pbase * 3 + i];
    for (int i = tid; i < 3 * H; i += 256) Ws[i] = W0[i];     // W0 (3x128)
    if (tid < H)  bbuf[tid] = b0[tid];
    if (tid < 64) b3s[tid] = (tid < 59) ? b3[tid] : 0.0f;
    __syncthreads();

    float amn0 = __ldg(aabb_min + 0), amn1 = __ldg(aabb_min + 1), amn2 = __ldg(aabb_min + 2);
    float amx0 = __ldg(aabb_max + 0), amx1 = __ldg(aabb_max + 1), amx2 = __ldg(aabb_max + 2);
    float sc0 = 2.0f / (amx0 - amn0), sc1 = 2.0f / (amx1 - amn1), sc2 = 2.0f / (amx2 - amn2);

    const int ty = tid >> 4;      // 0..15 : point group (8 points)
    const int tx = tid & 15;      // 0..15 : output group (8 cols)

    // ================= layer 0 : 3 -> 128, softplus =================
    {
        float xn[8][3];
        #pragma unroll
        for (int i = 0; i < 8; ++i) {
            int p = ty * 8 + i;
            xn[i][0] = (xs[p * 3 + 0] - amn0) * sc0 - 1.0f;
            xn[i][1] = (xs[p * 3 + 1] - amn1) * sc1 - 1.0f;
            xn[i][2] = (xs[p * 3 + 2] - amn2) * sc2 - 1.0f;
        }
        float acc[8][8];
        #pragma unroll
        for (int i = 0; i < 8; ++i)
            #pragma unroll
            for (int j = 0; j < 8; ++j) acc[i][j] = bbuf[tx * 8 + j];
        #pragma unroll
        for (int k = 0; k < 3; ++k) {
            float w[8];
            #pragma unroll
            for (int j = 0; j < 8; ++j) w[j] = Ws[k * H + tx * 8 + j];
            #pragma unroll
            for (int i = 0; i < 8; ++i)
                #pragma unroll
                for (int j = 0; j < 8; ++j) acc[i][j] += xn[i][k] * w[j];
        }
        __syncthreads();    // everyone done reading Ws (W0) before layer1 overwrites
        #pragma unroll
        for (int i = 0; i < 8; ++i)
            #pragma unroll
            for (int j = 0; j < 8; ++j)
                As[(ty * 8 + i) * SA + tx * 8 + j] = sp(acc[i][j]);
        __syncthreads();
    }

    // ================= layers 1,2 : 128 -> 128, softplus =================
    for (int layer = 0; layer < 2; ++layer) {
        const float* Wp = (layer == 0) ? W1 : W2;
        const float* bp = (layer == 0) ? b1 : b2;
        const float4* Wg = (const float4*)Wp;
        #pragma unroll
        for (int idx = tid; idx < (H * H) / 4; idx += 256)
            ((float4*)Ws)[idx] = Wg[idx];
        if (tid < H) bbuf[tid] = bp[tid];
        __syncthreads();

        float acc[8][8];
        #pragma unroll
        for (int i = 0; i < 8; ++i)
            #pragma unroll
            for (int j = 0; j < 8; ++j) acc[i][j] = 0.0f;

        for (int k = 0; k < H; ++k) {
            float a[8];
            #pragma unroll
            for (int i = 0; i < 8; ++i) a[i] = As[(ty * 8 + i) * SA + k];
            float4 w0v = *(const float4*)&Ws[k * H + tx * 8];
            float4 w1v = *(const float4*)&Ws[k * H + tx * 8 + 4];
            float w[8] = {w0v.x, w0v.y, w0v.z, w0v.w, w1v.x, w1v.y, w1v.z, w1v.w};
            #pragma unroll
            for (int i = 0; i < 8; ++i)
                #pragma unroll
                for (int j = 0; j < 8; ++j) acc[i][j] += a[i] * w[j];
        }
        __syncthreads();            // all K-loop reads of As complete
        float bj[8];
        #pragma unroll
        for (int j = 0; j < 8; ++j) bj[j] = bbuf[tx * 8 + j];
        #pragma unroll
        for (int i = 0; i < 8; ++i)
            #pragma unroll
            for (int j = 0; j < 8; ++j)
                As[(ty * 8 + i) * SA + tx * 8 + j] = sp(acc[i][j] + bj[j]);
        __syncthreads();
    }

    // ================= layer 3 : 128 -> 59 (padded 64), linear =================
    {
        // load W3 into Ws as [k][64], zero-padded
        for (int idx = tid; idx < H * 64; idx += 256) {
            int k = idx >> 6, j = idx & 63;
            Ws[idx] = (j < 59) ? __ldg(W3 + k * 59 + j) : 0.0f;
        }
        __syncthreads();

        const int tx8  = tid & 7;    // 8 groups of 8 cols
        const int ty32 = tid >> 3;   // 32 groups of 4 points
        float acc[4][8];
        #pragma unroll
        for (int i = 0; i < 4; ++i)
            #pragma unroll
            for (int j = 0; j < 8; ++j) acc[i][j] = 0.0f;

        for (int k = 0; k < H; ++k) {
            float a[4];
            #pragma unroll
            for (int i = 0; i < 4; ++i) a[i] = As[(ty32 * 4 + i) * SA + k];
            float4 w0v = *(const float4*)&Ws[k * 64 + tx8 * 8];
            float4 w1v = *(const float4*)&Ws[k * 64 + tx8 * 8 + 4];
            float w[8] = {w0v.x, w0v.y, w0v.z, w0v.w, w1v.x, w1v.y, w1v.z, w1v.w};
            #pragma unroll
            for (int i = 0; i < 4; ++i)
                #pragma unroll
                for (int j = 0; j < 8; ++j) acc[i][j] += a[i] * w[j];
        }
        __syncthreads();
        #pragma unroll
        for (int i = 0; i < 4; ++i)
            #pragma unroll
            for (int j = 0; j < 8; ++j)
                As[(ty32 * 4 + i) * SA + tx8 * 8 + j] = acc[i][j] + b3s[tx8 * 8 + j];
        __syncthreads();
    }

    // ================= epilogue : one thread per point =================
    if (tid < TILE) {
        const int p  = tid;
        const int pg = pbase + p;

        float x[59];
        #pragma unroll
        for (int j = 0; j < 59; ++j) x[j] = As[p * SA + j];

        float P[NB];
        // root: p[1,2,3] = s0 * softmax(x[1..3]); p[0] = 1 - s0
        {
            float s0 = sigf(x[0]);
            float o1, o2, o3;
            sm3(x[1], x[2], x[3], o1, o2, o3);
            P[1] = s0 * o1; P[2] = s0 * o2; P[3] = s0 * o3;
            P[0] = 1.0f - s0;
        }
#define BR(par, ch) { float a_ = P[par]; float s_ = sigf(x[ch]); \
                      P[ch] = a_ * s_; P[par] = a_ * (1.0f - s_); }
#define SUB3(par, gate, c1, c2, c3) { float a_ = P[par]; float g_ = sigf(x[gate]); \
        float o1_, o2_, o3_; sm3(x[c1], x[c2], x[c3], o1_, o2_, o3_); \
        P[c1] = a_ * g_ * o1_; P[c2] = a_ * g_ * o2_; P[c3] = a_ * g_ * o3_; \
        P[par] = a_ * (1.0f - g_); }
#define SUB5(par, gate, c1, c2, c3, c4, c5) { float a_ = P[par]; float g_ = sigf(x[gate]); \
        float o1_, o2_, o3_, o4_, o5_; sm5(x[c1], x[c2], x[c3], x[c4], x[c5], o1_, o2_, o3_, o4_, o5_); \
        P[c1] = a_ * g_ * o1_; P[c2] = a_ * g_ * o2_; P[c3] = a_ * g_ * o3_; \
        P[c4] = a_ * g_ * o4_; P[c5] = a_ * g_ * o5_; P[par] = a_ * (1.0f - g_); }

        BR(1, 4)  BR(2, 5)  BR(3, 6)
        BR(4, 7)  BR(5, 8)  BR(6, 9)
        BR(7, 10) BR(8, 11)
        SUB3(9, 55, 12, 13, 14)
        BR(12, 15)
        BR(13, 16) BR(14, 17)
        BR(16, 18) BR(17, 19)
        BR(18, 20) BR(19, 21)
        SUB3(15, 56, 22, 23, 24)
        SUB5(20, 57, 25, 28, 31, 34, 37)
        SUB5(21, 58, 40, 43, 46, 49, 52)
        BR(25, 26) BR(28, 29) BR(31, 32) BR(34, 35) BR(37, 38)
        BR(26, 27) BR(29, 30) BR(32, 33) BR(35, 36) BR(38, 39)
        BR(40, 41) BR(43, 44) BR(46, 47) BR(49, 50) BR(52, 53)
        BR(41, 42) BR(44, 45) BR(47, 48) BR(50, 51) BR(53, 54)
#undef BR
#undef SUB3
#undef SUB5

        // blended transform T = sum_b P[b] * tfs[b]
        float T[16];
        #pragma unroll
        for (int t = 0; t < 16; ++t) T[t] = 0.0f;
        #pragma unroll
        for (int b = 0; b < NB; ++b) {
            float w = P[b];
            #pragma unroll
            for (int t = 0; t < 16; ++t) T[t] += w * tfs_s[b * 16 + t];
        }

        float X = xs[p * 3 + 0], Y = xs[p * 3 + 1], Z = xs[p * 3 + 2];
        float xb0 = T[0]  * X + T[1]  * Y + T[2]  * Z + T[3];
        float xb1 = T[4]  * X + T[5]  * Y + T[6]  * Z + T[7];
        float xb2 = T[8]  * X + T[9]  * Y + T[10] * Z + T[11];

        // rot_hat from quats
        float4 qv = *(const float4*)(quats + (size_t)pg * 4);
        {
            float inv = rsqrtf(qv.x * qv.x + qv.y * qv.y + qv.z * qv.z + qv.w * qv.w);
            qv.x *= inv; qv.y *= inv; qv.z *= inv; qv.w *= inv;
        }
        float r = qv.x, xq = qv.y, yq = qv.z, zq = qv.w;
        float R[3][3];
        R[0][0] = 1.0f - 2.0f * (yq * yq + zq * zq);
        R[0][1] = 2.0f * (xq * yq - r * zq);
        R[0][2] = 2.0f * (xq * zq + r * yq);
        R[1][0] = 2.0f * (xq * yq + r * zq);
        R[1][1] = 1.0f - 2.0f * (xq * xq + zq * zq);
        R[1][2] = 2.0f * (yq * zq - r * xq);
        R[2][0] = 2.0f * (xq * zq - r * yq);
        R[2][1] = 2.0f * (yq * zq + r * xq);
        R[2][2] = 1.0f - 2.0f * (xq * xq + yq * yq);

        float rb[3][3];
        #pragma unroll
        for (int i = 0; i < 3; ++i)
            #pragma unroll
            for (int k = 0; k < 3; ++k)
                rb[i][k] = T[i * 4 + 0] * R[0][k] + T[i * 4 + 1] * R[1][k] + T[i * 4 + 2] * R[2][k];

        // mat_to_quat
        float m00 = rb[0][0], m01 = rb[0][1], m02 = rb[0][2];
        float m10 = rb[1][0], m11 = rb[1][1], m12 = rb[1][2];
        float m20 = rb[2][0], m21 = rb[2][1], m22 = rb[2][2];
        float t0 = 1.0f + m00 + m11 + m22;
        float t1 = 1.0f + m00 - m11 - m22;
        float t2 = 1.0f - m00 + m11 - m22;
        float t3 = 1.0f - m00 - m11 + m22;

        int best = 0; float tb = t0;
        if (t1 > tb) { best = 1; tb = t1; }
        if (t2 > tb) { best = 2; tb = t2; }
        if (t3 > tb) { best = 3; tb = t3; }

        float qa, qb2, qc, qd;
        if (best == 0)      { qa = t0;        qb2 = m21 - m12; qc = m02 - m20; qd = m10 - m01; }
        else if (best == 1) { qa = m21 - m12; qb2 = t1;        qc = m01 + m10; qd = m02 + m20; }
        else if (best == 2) { qa = m02 - m20; qb2 = m01 + m10; qc = t2;        qd = m12 + m21; }
        else                { qa = m10 - m01; qb2 = m02 + m20; qc = m12 + m21; qd = t3;        }
        float scale = 0.5f * rsqrtf(fmaxf(tb, 1e-8f));
        qa *= scale; qb2 *= scale; qc *= scale; qd *= scale;
        float qinv = rsqrtf(qa * qa + qb2 * qb2 + qc * qc + qd * qd);
        qa *= qinv; qb2 *= qinv; qc *= qinv; qd *= qinv;

        // ---- outputs: x_bar | rot_bar | quat_bar | T_fwd ----
        const size_t n = (size_t)Npts;
        out[(size_t)pg * 3 + 0] = xb0;
        out[(size_t)pg * 3 + 1] = xb1;
        out[(size_t)pg * 3 + 2] = xb2;
        float* ro = out + 3 * n + (size_t)pg * 9;
        #pragma unroll
        for (int i = 0; i < 3; ++i)
            #pragma unroll
            for (int k = 0; k < 3; ++k) ro[i * 3 + k] = rb[i][k];
        float* qo = out + 12 * n + (size_t)pg * 4;
        qo[0] = qa; qo[1] = qb2; qo[2] = qc; qo[3] = qd;
        float* to = out + 16 * n + (size_t)pg * 16;
        #pragma unroll
        for (int t = 0; t < 16; ++t) to[t] = T[t];
    }
}

extern "C" void kernel_launch(void* const* d_in, const int* in_sizes, int n_in,
                              void* d_out, int out_size)
{
    const float* xyz      = (const float*)d_in[0];
    const float* quats    = (const float*)d_in[1];
    const float* tfs      = (const float*)d_in[2];
    const float* aabb_min = (const float*)d_in[3];
    const float* aabb_max = (const float*)d_in[4];
    const float* W0 = (const float*)d_in[5];
    const float* b0 = (const float*)d_in[6];
    const float* W1 = (const float*)d_in[7];
    const float* b1 = (const float*)d_in[8];
    const float* W2 = (const float*)d_in[9];
    const float* b2 = (const float*)d_in[10];
    const float* W3 = (const float*)d_in[11];
    const float* b3 = (const float*)d_in[12];
    float* out = (float*)d_out;

    int Npts = in_sizes[0] / 3;
    int grid = Npts / TILE;

    const size_t smem_bytes =
        (size_t)(TILE * SA + H * H + TILE * 3 + NB * 16 + H + 64) * sizeof(float);

    cudaFuncSetAttribute(skin_kernel,
                         cudaFuncAttributeMaxDynamicSharedMemorySize,
                         (int)smem_bytes);

    skin_kernel<<<grid, 256, smem_bytes>>>(
        xyz, quats, tfs, aabb_min, aabb_max,
        W0, b0, W1, b1, W2, b2, W3, b3, out, Npts);
}

// round 3
// speedup vs baseline: 2.9636x; 2.9636x over previous
#include <cuda_runtime.h>
#include <cuda_bf16.h>
#include <stdint.h>

// SkinningField R3: warp-level bf16 mma.sync (plain sm_103 PTX), split-bf16 3-pass,
// activations register-resident (D-frag == next A-frag relabel), persistent CTAs.

#define H    128
#define NB   55
#define TILE 128          // points per CTA iteration (8 warps x 16 rows)

// padded weight row stride (bf16 elems): 136*2 = 272B -> conflict-free ldmatrix
#define WSTR 136

// smem byte offsets
#define OFF_W1H 0
#define OFF_W1L 34816
#define OFF_W2H 69632
#define OFF_W2L 104448
#define OFF_W3H 139264
#define OFF_W3L 156672
#define OFF_W0  174080                 // 384 floats
#define OFF_B0  (OFF_W0 + 1536)       // 128 floats
#define OFF_B1  (OFF_B0 + 512)
#define OFF_B2  (OFF_B1 + 512)
#define OFF_B3  (OFF_B2 + 512)        // 64 floats
#define OFF_TFS (OFF_B3 + 256)        // 880 floats
#define OFF_ES  (OFF_TFS + 3520)      // 8 warps * 16*65 floats = 33280B
#define SMEM_TOTAL (OFF_ES + 8 * 16 * 65 * 4)   // 214208

struct __align__(16) WBlob {
    __nv_bfloat16 w1h[128 * WSTR], w1l[128 * WSTR];
    __nv_bfloat16 w2h[128 * WSTR], w2l[128 * WSTR];
    __nv_bfloat16 w3h[64 * WSTR],  w3l[64 * WSTR];
};
__device__ WBlob g_wt;    // zero-init, written by prep kernel

// ---------------- helpers ----------------
__device__ __forceinline__ uint32_t smem_u32(const void* p) {
    uint32_t a;
    asm("{ .reg .u64 t; cvta.to.shared.u64 t, %1; cvt.u32.u64 %0, t; }" : "=r"(a) : "l"(p));
    return a;
}
__device__ __forceinline__ float sigf(float v) { return 1.0f / (1.0f + __expf(-v)); }
__device__ __forceinline__ float sp(float v) {
    return fmaxf(v, 0.0f) + __logf(1.0f + __expf(-fabsf(v)));
}
__device__ __forceinline__ void sm3(float a, float b, float c, float& oa, float& ob, float& oc) {
    float m = fmaxf(a, fmaxf(b, c));
    float ea = __expf(a - m), eb = __expf(b - m), ec = __expf(c - m);
    float inv = 1.0f / (ea + eb + ec);
    oa = ea * inv; ob = eb * inv; oc = ec * inv;
}
__device__ __forceinline__ void sm5(float a, float b, float c, float d, float e,
                                    float& oa, float& ob, float& oc, float& od, float& oe) {
    float m = fmaxf(fmaxf(a, b), fmaxf(fmaxf(c, d), e));
    float ea = __expf(a - m), eb = __expf(b - m), ec = __expf(c - m),
          ed = __expf(d - m), ee = __expf(e - m);
    float inv = 1.0f / (ea + eb + ec + ed + ee);
    oa = ea * inv; ob = eb * inv; oc = ec * inv; od = ed * inv; oe = ee * inv;
}
// pack (h0,h1) -> bf16x2 hi word (h0 in low half); lo word = residuals
__device__ __forceinline__ uint32_t pack_split(float h0, float h1, uint32_t& wlo) {
    uint32_t whi;
    asm("cvt.rn.bf16x2.f32 %0, %1, %2;" : "=r"(whi) : "f"(h1), "f"(h0));
    float r0 = __uint_as_float(whi << 16);
    float r1 = __uint_as_float(whi & 0xffff0000u);
    float l0 = h0 - r0, l1 = h1 - r1;
    asm("cvt.rn.bf16x2.f32 %0, %1, %2;" : "=r"(wlo) : "f"(l1), "f"(l0));
    return whi;
}

__device__ __forceinline__ void mma_bf16(float& d0, float& d1, float& d2, float& d3,
                                         uint32_t a0, uint32_t a1, uint32_t a2, uint32_t a3,
                                         uint32_t b0, uint32_t b1) {
    asm volatile("mma.sync.aligned.m16n8k16.row.col.f32.bf16.bf16.f32 "
                 "{%0,%1,%2,%3}, {%4,%5,%6,%7}, {%8,%9}, {%0,%1,%2,%3};"
                 : "+f"(d0), "+f"(d1), "+f"(d2), "+f"(d3)
                 : "r"(a0), "r"(a1), "r"(a2), "r"(a3), "r"(b0), "r"(b1));
}

// ldmatrix x4: m0=(n0..n0+7, k0..k0+7) m1=(n0.., k0+8..) m2=(n0+8.., k0..) m3=(n0+8.., k0+8..)
// -> {r0,r1} = B-frag for n-chunk n0/8, {r2,r3} = n-chunk n0/8+1
__device__ __forceinline__ void ldx4(uint32_t b[4], uint32_t base, int lane, int n0, int k0) {
    int grp = lane >> 3, r = lane & 7;
    int row = n0 + r + ((grp >> 1) << 3);
    int col = k0 + ((grp & 1) << 3);
    uint32_t addr = base + (uint32_t)(row * WSTR + col) * 2u;
    asm volatile("ldmatrix.sync.aligned.m8n8.x4.shared.b16 {%0,%1,%2,%3}, [%4];"
                 : "=r"(b[0]), "=r"(b[1]), "=r"(b[2]), "=r"(b[3]) : "r"(addr));
}

// NC = number of n8 accumulator chunks (16 for 128-wide, 8 for 64-wide)
template <int NC>
__device__ __forceinline__ void gemm_layer(float acc[][4],
                                           const uint32_t ahi[8][4], const uint32_t alo[8][4],
                                           uint32_t whi, uint32_t wlo, int lane) {
    #pragma unroll
    for (int j = 0; j < NC; ++j) { acc[j][0] = 0.f; acc[j][1] = 0.f; acc[j][2] = 0.f; acc[j][3] = 0.f; }
    #pragma unroll
    for (int kk = 0; kk < 8; ++kk) {
        #pragma unroll
        for (int jj = 0; jj < NC / 2; ++jj) {
            uint32_t bh[4], bl[4];
            ldx4(bh, whi, lane, 16 * jj, 16 * kk);
            ldx4(bl, wlo, lane, 16 * jj, 16 * kk);
            float* aL = acc[2 * jj];
            float* aR = acc[2 * jj + 1];
            mma_bf16(aL[0], aL[1], aL[2], aL[3], ahi[kk][0], ahi[kk][1], ahi[kk][2], ahi[kk][3], bh[0], bh[1]);
            mma_bf16(aR[0], aR[1], aR[2], aR[3], ahi[kk][0], ahi[kk][1], ahi[kk][2], ahi[kk][3], bh[2], bh[3]);
            mma_bf16(aL[0], aL[1], aL[2], aL[3], ahi[kk][0], ahi[kk][1], ahi[kk][2], ahi[kk][3], bl[0], bl[1]);
            mma_bf16(aR[0], aR[1], aR[2], aR[3], ahi[kk][0], ahi[kk][1], ahi[kk][2], ahi[kk][3], bl[2], bl[3]);
            mma_bf16(aL[0], aL[1], aL[2], aL[3], alo[kk][0], alo[kk][1], alo[kk][2], alo[kk][3], bh[0], bh[1]);
            mma_bf16(aR[0], aR[1], aR[2], aR[3], alo[kk][0], alo[kk][1], alo[kk][2], alo[kk][3], bh[2], bh[3]);
        }
    }
}

// bias + softplus + split-pack acc(16 chunks) -> next-layer A frags
__device__ __forceinline__ void act_pack(const float acc[][4], const float* bias_s,
                                         uint32_t ahi[8][4], uint32_t alo[8][4], int lane) {
    const int cbase = 2 * (lane & 3);
    #pragma unroll
    for (int j = 0; j < 16; ++j) {
        int c = 8 * j + cbase;
        float h0 = sp(acc[j][0] + bias_s[c]);
        float h1 = sp(acc[j][1] + bias_s[c + 1]);
        float h2 = sp(acc[j][2] + bias_s[c]);
        float h3 = sp(acc[j][3] + bias_s[c + 1]);
        uint32_t l01, l23;
        uint32_t h01 = pack_split(h0, h1, l01);
        uint32_t h23 = pack_split(h2, h3, l23);
        int kk = j >> 1, half = (j & 1) << 1;
        ahi[kk][half] = h01; ahi[kk][half + 1] = h23;
        alo[kk][half] = l01; alo[kk][half + 1] = l23;
    }
}

// ---------------- prep: transpose + split weights into g_wt ----------------
__global__ void prep_kernel(const float* __restrict__ W1, const float* __restrict__ W2,
                            const float* __restrict__ W3) {
    int tid = threadIdx.x;
    __nv_bfloat16 z = __float2bfloat16(0.0f);
    for (int i = tid; i < 64 * WSTR; i += 256) { g_wt.w3h[i] = z; g_wt.w3l[i] = z; }
    __syncthreads();
    for (int i = tid; i < H * H; i += 256) {
        int k = i >> 7, n = i & 127;
        int o = n * WSTR + k;
        float f1 = W1[i];
        __nv_bfloat16 h1 = __float2bfloat16(f1);
        g_wt.w1h[o] = h1; g_wt.w1l[o] = __float2bfloat16(f1 - __bfloat162float(h1));
        float f2 = W2[i];
        __nv_bfloat16 h2 = __float2bfloat16(f2);
        g_wt.w2h[o] = h2; g_wt.w2l[o] = __float2bfloat16(f2 - __bfloat162float(h2));
    }
    for (int i = tid; i < H * 59; i += 256) {
        int k = i / 59, n = i % 59;
        int o = n * WSTR + k;
        float f = W3[i];
        __nv_bfloat16 hh = __float2bfloat16(f);
        g_wt.w3h[o] = hh; g_wt.w3l[o] = __float2bfloat16(f - __bfloat162float(hh));
    }
}

// ---------------- main kernel ----------------
__global__ void __launch_bounds__(256, 1)
skin_mma_kernel(const float* __restrict__ xyz,  const float* __restrict__ quats,
                const float* __restrict__ tfs,  const float* __restrict__ aabb_min,
                const float* __restrict__ aabb_max,
                const float* __restrict__ W0, const float* __restrict__ b0,
                const float* __restrict__ b1, const float* __restrict__ b2,
                const float* __restrict__ b3,
                float* __restrict__ out, int Npts, int ntiles)
{
    extern __shared__ char smem[];
    const int tid  = threadIdx.x;
    const int wid  = tid >> 5;
    const int lane = tid & 31;

    // stage weight blob
    {
        const uint4* src = (const uint4*)&g_wt;
        uint4* dst = (uint4*)smem;
        for (int i = tid; i < (int)(sizeof(WBlob) / 16); i += 256) dst[i] = src[i];
    }
    float* w0s  = (float*)(smem + OFF_W0);
    float* b0s  = (float*)(smem + OFF_B0);
    float* b1s  = (float*)(smem + OFF_B1);
    float* b2s  = (float*)(smem + OFF_B2);
    float* b3s  = (float*)(smem + OFF_B3);
    float* tfs_s = (float*)(smem + OFF_TFS);
    for (int i = tid; i < 3 * H; i += 256) w0s[i] = W0[i];
    if (tid < H) { b0s[tid] = b0[tid]; b1s[tid] = b1[tid]; b2s[tid] = b2[tid]; }
    if (tid < 64) b3s[tid] = (tid < 59) ? b3[tid] : 0.0f;
    for (int i = tid; i < NB * 16; i += 256) tfs_s[i] = tfs[i];
    __syncthreads();

    const uint32_t u_w1h = smem_u32(smem + OFF_W1H), u_w1l = smem_u32(smem + OFF_W1L);
    const uint32_t u_w2h = smem_u32(smem + OFF_W2H), u_w2l = smem_u32(smem + OFF_W2L);
    const uint32_t u_w3h = smem_u32(smem + OFF_W3H), u_w3l = smem_u32(smem + OFF_W3L);
    float* es_w = (float*)(smem + OFF_ES) + wid * (16 * 65);

    const float amn0 = __ldg(aabb_min + 0), amn1 = __ldg(aabb_min + 1), amn2 = __ldg(aabb_min + 2);
    const float amx0 = __ldg(aabb_max + 0), amx1 = __ldg(aabb_max + 1), amx2 = __ldg(aabb_max + 2);
    const float sc0 = 2.0f / (amx0 - amn0), sc1 = 2.0f / (amx1 - amn1), sc2 = 2.0f / (amx2 - amn2);

    const int g = lane >> 2;          // row group 0..7
    const int cbase = 2 * (lane & 3);

    for (int t = blockIdx.x; t < ntiles; t += gridDim.x) {
        const int pbase = t * TILE + wid * 16;

        uint32_t ahi[8][4], alo[8][4];
        float acc[16][4];

        // ---- layer 0: 3 -> 128 in fp32, direct to A-frags ----
        {
            const int pA = pbase + g, pB = pbase + g + 8;
            float xA0 = (xyz[(size_t)pA * 3 + 0] - amn0) * sc0 - 1.0f;
            float xA1 = (xyz[(size_t)pA * 3 + 1] - amn1) * sc1 - 1.0f;
            float xA2 = (xyz[(size_t)pA * 3 + 2] - amn2) * sc2 - 1.0f;
            float xB0 = (xyz[(size_t)pB * 3 + 0] - amn0) * sc0 - 1.0f;
            float xB1 = (xyz[(size_t)pB * 3 + 1] - amn1) * sc1 - 1.0f;
            float xB2 = (xyz[(size_t)pB * 3 + 2] - amn2) * sc2 - 1.0f;
            #pragma unroll
            for (int j = 0; j < 16; ++j) {
                int c = 8 * j + cbase;
                float w0c = w0s[c],     w1c = w0s[128 + c],     w2c = w0s[256 + c];
                float w0d = w0s[c + 1], w1d = w0s[128 + c + 1], w2d = w0s[256 + c + 1];
                float h0 = sp(b0s[c]     + xA0 * w0c + xA1 * w1c + xA2 * w2c);
                float h1 = sp(b0s[c + 1] + xA0 * w0d + xA1 * w1d + xA2 * w2d);
                float h2 = sp(b0s[c]     + xB0 * w0c + xB1 * w1c + xB2 * w2c);
                float h3 = sp(b0s[c + 1] + xB0 * w0d + xB1 * w1d + xB2 * w2d);
                uint32_t l01, l23;
                uint32_t h01 = pack_split(h0, h1, l01);
                uint32_t h23 = pack_split(h2, h3, l23);
                int kk = j >> 1, half = (j & 1) << 1;
                ahi[kk][half] = h01; ahi[kk][half + 1] = h23;
                alo[kk][half] = l01; alo[kk][half + 1] = l23;
            }
        }

        // ---- layers 1, 2 ----
        gemm_layer<16>(acc, ahi, alo, u_w1h, u_w1l, lane);
        act_pack(acc, b1s, ahi, alo, lane);
        gemm_layer<16>(acc, ahi, alo, u_w2h, u_w2l, lane);
        act_pack(acc, b2s, ahi, alo, lane);

        // ---- layer 3: N=64 ----
        gemm_layer<8>(acc, ahi, alo, u_w3h, u_w3l, lane);

        // stage logits to smem (per-warp region), transpose to per-point
        __syncwarp();
        #pragma unroll
        for (int j = 0; j < 8; ++j) {
            int c = 8 * j + cbase;
            es_w[g * 65 + c]           = acc[j][0] + b3s[c];
            es_w[g * 65 + c + 1]       = acc[j][1] + b3s[c + 1];
            es_w[(g + 8) * 65 + c]     = acc[j][2] + b3s[c];
            es_w[(g + 8) * 65 + c + 1] = acc[j][3] + b3s[c + 1];
        }
        __syncwarp();

        // ---- epilogue: lanes 0..15, one point each ----
        if (lane < 16) {
            const int pg = pbase + lane;
            float x[59];
            #pragma unroll
            for (int j = 0; j < 59; ++j) x[j] = es_w[lane * 65 + j];

            float P[NB];
            {
                float s0 = sigf(x[0]);
                float o1, o2, o3;
                sm3(x[1], x[2], x[3], o1, o2, o3);
                P[1] = s0 * o1; P[2] = s0 * o2; P[3] = s0 * o3;
                P[0] = 1.0f - s0;
            }
#define BR(par, ch) { float a_ = P[par]; float s_ = sigf(x[ch]); \
                      P[ch] = a_ * s_; P[par] = a_ * (1.0f - s_); }
#define SUB3(par, gate, c1, c2, c3) { float a_ = P[par]; float g_ = sigf(x[gate]); \
        float o1_, o2_, o3_; sm3(x[c1], x[c2], x[c3], o1_, o2_, o3_); \
        P[c1] = a_ * g_ * o1_; P[c2] = a_ * g_ * o2_; P[c3] = a_ * g_ * o3_; \
        P[par] = a_ * (1.0f - g_); }
#define SUB5(par, gate, c1, c2, c3, c4, c5) { float a_ = P[par]; float g_ = sigf(x[gate]); \
        float o1_, o2_, o3_, o4_, o5_; sm5(x[c1], x[c2], x[c3], x[c4], x[c5], o1_, o2_, o3_, o4_, o5_); \
        P[c1] = a_ * g_ * o1_; P[c2] = a_ * g_ * o2_; P[c3] = a_ * g_ * o3_; \
        P[c4] = a_ * g_ * o4_; P[c5] = a_ * g_ * o5_; P[par] = a_ * (1.0f - g_); }

            BR(1, 4)  BR(2, 5)  BR(3, 6)
            BR(4, 7)  BR(5, 8)  BR(6, 9)
            BR(7, 10) BR(8, 11)
            SUB3(9, 55, 12, 13, 14)
            BR(12, 15)
            BR(13, 16) BR(14, 17)
            BR(16, 18) BR(17, 19)
            BR(18, 20) BR(19, 21)
            SUB3(15, 56, 22, 23, 24)
            SUB5(20, 57, 25, 28, 31, 34, 37)
            SUB5(21, 58, 40, 43, 46, 49, 52)
            BR(25, 26) BR(28, 29) BR(31, 32) BR(34, 35) BR(37, 38)
            BR(26, 27) BR(29, 30) BR(32, 33) BR(35, 36) BR(38, 39)
            BR(40, 41) BR(43, 44) BR(46, 47) BR(49, 50) BR(52, 53)
            BR(41, 42) BR(44, 45) BR(47, 48) BR(50, 51) BR(53, 54)
#undef BR
#undef SUB3
#undef SUB5

            float T[16];
            #pragma unroll
            for (int q = 0; q < 16; ++q) T[q] = 0.0f;
            #pragma unroll
            for (int b = 0; b < NB; ++b) {
                float w = P[b];
                #pragma unroll
                for (int q = 0; q < 16; ++q) T[q] += w * tfs_s[b * 16 + q];
            }

            float X = xyz[(size_t)pg * 3 + 0];
            float Y = xyz[(size_t)pg * 3 + 1];
            float Z = xyz[(size_t)pg * 3 + 2];
            float xb0 = T[0] * X + T[1] * Y + T[2]  * Z + T[3];
            float xb1 = T[4] * X + T[5] * Y + T[6]  * Z + T[7];
            float xb2 = T[8] * X + T[9] * Y + T[10] * Z + T[11];

            float4 qv = *(const float4*)(quats + (size_t)pg * 4);
            {
                float inv = rsqrtf(qv.x * qv.x + qv.y * qv.y + qv.z * qv.z + qv.w * qv.w);
                qv.x *= inv; qv.y *= inv; qv.z *= inv; qv.w *= inv;
            }
            float r = qv.x, xq = qv.y, yq = qv.z, zq = qv.w;
            float R[3][3];
            R[0][0] = 1.0f - 2.0f * (yq * yq + zq * zq);
            R[0][1] = 2.0f * (xq * yq - r * zq);
            R[0][2] = 2.0f * (xq * zq + r * yq);
            R[1][0] = 2.0f * (xq * yq + r * zq);
            R[1][1] = 1.0f - 2.0f * (xq * xq + zq * zq);
            R[1][2] = 2.0f * (yq * zq - r * xq);
            R[2][0] = 2.0f * (xq * zq - r * yq);
            R[2][1] = 2.0f * (yq * zq + r * xq);
            R[2][2] = 1.0f - 2.0f * (xq * xq + yq * yq);

            float rb[3][3];
            #pragma unroll
            for (int i = 0; i < 3; ++i)
                #pragma unroll
                for (int k = 0; k < 3; ++k)
                    rb[i][k] = T[i * 4 + 0] * R[0][k] + T[i * 4 + 1] * R[1][k] + T[i * 4 + 2] * R[2][k];

            float m00 = rb[0][0], m01 = rb[0][1], m02 = rb[0][2];
            float m10 = rb[1][0], m11 = rb[1][1], m12 = rb[1][2];
            float m20 = rb[2][0], m21 = rb[2][1], m22 = rb[2][2];
            float t0 = 1.0f + m00 + m11 + m22;
            float t1 = 1.0f + m00 - m11 - m22;
            float t2 = 1.0f - m00 + m11 - m22;
            float t3 = 1.0f - m00 - m11 + m22;

            int best = 0; float tb = t0;
            if (t1 > tb) { best = 1; tb = t1; }
            if (t2 > tb) { best = 2; tb = t2; }
            if (t3 > tb) { best = 3; tb = t3; }

            float qa, qb2, qc, qd;
            if (best == 0)      { qa = t0;        qb2 = m21 - m12; qc = m02 - m20; qd = m10 - m01; }
            else if (best == 1) { qa = m21 - m12; qb2 = t1;        qc = m01 + m10; qd = m02 + m20; }
            else if (best == 2) { qa = m02 - m20; qb2 = m01 + m10; qc = t2;        qd = m12 + m21; }
            else                { qa = m10 - m01; qb2 = m02 + m20; qc = m12 + m21; qd = t3;        }
            float scale = 0.5f * rsqrtf(fmaxf(tb, 1e-8f));
            qa *= scale; qb2 *= scale; qc *= scale; qd *= scale;
            float qinv = rsqrtf(qa * qa + qb2 * qb2 + qc * qc + qd * qd);
            qa *= qinv; qb2 *= qinv; qc *= qinv; qd *= qinv;

            const size_t n = (size_t)Npts;
            out[(size_t)pg * 3 + 0] = xb0;
            out[(size_t)pg * 3 + 1] = xb1;
            out[(size_t)pg * 3 + 2] = xb2;
            float* ro = out + 3 * n + (size_t)pg * 9;
            #pragma unroll
            for (int i = 0; i < 3; ++i)
                #pragma unroll
                for (int k = 0; k < 3; ++k) ro[i * 3 + k] = rb[i][k];
            float* qo = out + 12 * n + (size_t)pg * 4;
            qo[0] = qa; qo[1] = qb2; qo[2] = qc; qo[3] = qd;
            float* to = out + 16 * n + (size_t)pg * 16;
            #pragma unroll
            for (int q = 0; q < 16; ++q) to[q] = T[q];
        }
        __syncwarp();
    }
}

extern "C" void kernel_launch(void* const* d_in, const int* in_sizes, int n_in,
                              void* d_out, int out_size)
{
    const float* xyz      = (const float*)d_in[0];
    const float* quats    = (const float*)d_in[1];
    const float* tfs      = (const float*)d_in[2];
    const float* aabb_min = (const float*)d_in[3];
    const float* aabb_max = (const float*)d_in[4];
    const float* W0 = (const float*)d_in[5];
    const float* b0 = (const float*)d_in[6];
    const float* W1 = (const float*)d_in[7];
    const float* b1 = (const float*)d_in[8];
    const float* W2 = (const float*)d_in[9];
    const float* b2 = (const float*)d_in[10];
    const float* W3 = (const float*)d_in[11];
    const float* b3 = (const float*)d_in[12];
    float* out = (float*)d_out;

    int Npts = in_sizes[0] / 3;
    int ntiles = Npts / TILE;

    int sms = 0;
    cudaDeviceGetAttribute(&sms, cudaDevAttrMultiProcessorCount, 0);
    if (sms <= 0) sms = 148;
    int grid = (sms < ntiles) ? sms : ntiles;

    prep_kernel<<<1, 256>>>(W1, W2, W3);

    cudaFuncSetAttribute(skin_mma_kernel,
                         cudaFuncAttributeMaxDynamicSharedMemorySize, SMEM_TOTAL);
    skin_mma_kernel<<<grid, 256, SMEM_TOTAL>>>(
        xyz, quats, tfs, aabb_min, aabb_max,
        W0, b0, b1, b2, b3, out, Npts, ntiles);
}

// round 4
// speedup vs baseline: 4.0005x; 1.3499x over previous
#include <cuda_runtime.h>
#include <cuda_fp16.h>
#include <stdint.h>

// SkinningField R4: fp16 mma.sync 2-pass (B split hi/lo, A single fp16),
// 384 threads (12 warps, 3/SMSP), TILE=192, register-resident activations.

#define H    128
#define NB   55
#define TILE 192          // 12 warps x 16 points
#define NWARP 12
#define WSTR 136          // padded weight row stride (fp16 elems)
#define ESTR 61           // epilogue staging row stride (floats), gcd(61,32)=1

// smem byte offsets
#define OFF_W1H 0
#define OFF_W1L 34816
#define OFF_W2H 69632
#define OFF_W2L 104448
#define OFF_W3H 139264
#define OFF_W3L 156672
#define OFF_W0  174080                 // 384 floats
#define OFF_B0  (OFF_W0 + 1536)
#define OFF_B1  (OFF_B0 + 512)
#define OFF_B2  (OFF_B1 + 512)
#define OFF_B3  (OFF_B2 + 512)        // 64 floats
#define OFF_TFS (OFF_B3 + 256)        // 880 floats
#define OFF_ES  (OFF_TFS + 3520)
#define SMEM_TOTAL (OFF_ES + NWARP * 16 * ESTR * 4)   // 227776

struct __align__(16) WBlob {
    __half w1h[128 * WSTR], w1l[128 * WSTR];
    __half w2h[128 * WSTR], w2l[128 * WSTR];
    __half w3h[64 * WSTR],  w3l[64 * WSTR];
};
__device__ WBlob g_wt;

// ---------------- helpers ----------------
__device__ __forceinline__ uint32_t smem_u32(const void* p) {
    uint32_t a;
    asm("{ .reg .u64 t; cvta.to.shared.u64 t, %1; cvt.u32.u64 %0, t; }" : "=r"(a) : "l"(p));
    return a;
}
__device__ __forceinline__ float sigf(float v) { return 1.0f / (1.0f + __expf(-v)); }
__device__ __forceinline__ float sp(float v) {
    return fmaxf(v, 0.0f) + __logf(1.0f + __expf(-fabsf(v)));
}
__device__ __forceinline__ void sm3(float a, float b, float c, float& oa, float& ob, float& oc) {
    float m = fmaxf(a, fmaxf(b, c));
    float ea = __expf(a - m), eb = __expf(b - m), ec = __expf(c - m);
    float inv = 1.0f / (ea + eb + ec);
    oa = ea * inv; ob = eb * inv; oc = ec * inv;
}
__device__ __forceinline__ void sm5(float a, float b, float c, float d, float e,
                                    float& oa, float& ob, float& oc, float& od, float& oe) {
    float m = fmaxf(fmaxf(a, b), fmaxf(fmaxf(c, d), e));
    float ea = __expf(a - m), eb = __expf(b - m), ec = __expf(c - m),
          ed = __expf(d - m), ee = __expf(e - m);
    float inv = 1.0f / (ea + eb + ec + ed + ee);
    oa = ea * inv; ob = eb * inv; oc = ec * inv; od = ed * inv; oe = ee * inv;
}
// pack (h0,h1) -> fp16x2 (h0 low half)
__device__ __forceinline__ uint32_t pack_h2(float h0, float h1) {
    uint32_t w;
    asm("cvt.rn.f16x2.f32 %0, %1, %2;" : "=r"(w) : "f"(h1), "f"(h0));
    return w;
}

__device__ __forceinline__ void mma_f16(float& d0, float& d1, float& d2, float& d3,
                                        uint32_t a0, uint32_t a1, uint32_t a2, uint32_t a3,
                                        uint32_t b0, uint32_t b1) {
    asm volatile("mma.sync.aligned.m16n8k16.row.col.f32.f16.f16.f32 "
                 "{%0,%1,%2,%3}, {%4,%5,%6,%7}, {%8,%9}, {%0,%1,%2,%3};"
                 : "+f"(d0), "+f"(d1), "+f"(d2), "+f"(d3)
                 : "r"(a0), "r"(a1), "r"(a2), "r"(a3), "r"(b0), "r"(b1));
}

// ldmatrix x4: {b0,b1} = B-frag n-chunk n0/8, {b2,b3} = n-chunk n0/8+1
__device__ __forceinline__ void ldx4(uint32_t b[4], uint32_t base, int lane, int n0, int k0) {
    int grp = lane >> 3, r = lane & 7;
    int row = n0 + r + ((grp >> 1) << 3);
    int col = k0 + ((grp & 1) << 3);
    uint32_t addr = base + (uint32_t)(row * WSTR + col) * 2u;
    asm volatile("ldmatrix.sync.aligned.m8n8.x4.shared.b16 {%0,%1,%2,%3}, [%4];"
                 : "=r"(b[0]), "=r"(b[1]), "=r"(b[2]), "=r"(b[3]) : "r"(addr));
}

// 2-pass: D = Ahi*Bhi + Ahi*Blo  (error = A fp16 rounding only)
template <int NC>
__device__ __forceinline__ void gemm_layer(float acc[][4], const uint32_t ahi[8][4],
                                           uint32_t whi, uint32_t wlo, int lane) {
    #pragma unroll
    for (int j = 0; j < NC; ++j) { acc[j][0] = 0.f; acc[j][1] = 0.f; acc[j][2] = 0.f; acc[j][3] = 0.f; }
    #pragma unroll
    for (int kk = 0; kk < 8; ++kk) {
        #pragma unroll
        for (int jj = 0; jj < NC / 2; ++jj) {
            uint32_t bh[4], bl[4];
            ldx4(bh, whi, lane, 16 * jj, 16 * kk);
            ldx4(bl, wlo, lane, 16 * jj, 16 * kk);
            float* aL = acc[2 * jj];
            float* aR = acc[2 * jj + 1];
            mma_f16(aL[0], aL[1], aL[2], aL[3], ahi[kk][0], ahi[kk][1], ahi[kk][2], ahi[kk][3], bh[0], bh[1]);
            mma_f16(aR[0], aR[1], aR[2], aR[3], ahi[kk][0], ahi[kk][1], ahi[kk][2], ahi[kk][3], bh[2], bh[3]);
            mma_f16(aL[0], aL[1], aL[2], aL[3], ahi[kk][0], ahi[kk][1], ahi[kk][2], ahi[kk][3], bl[0], bl[1]);
            mma_f16(aR[0], aR[1], aR[2], aR[3], ahi[kk][0], ahi[kk][1], ahi[kk][2], ahi[kk][3], bl[2], bl[3]);
        }
    }
}

// bias + softplus + fp16 pack: acc(16 chunks) -> next-layer A frags
__device__ __forceinline__ void act_pack(const float acc[][4], const float* bias_s,
                                         uint32_t ahi[8][4], int lane) {
    const int cbase = 2 * (lane & 3);
    #pragma unroll
    for (int j = 0; j < 16; ++j) {
        int c = 8 * j + cbase;
        float h0 = sp(acc[j][0] + bias_s[c]);
        float h1 = sp(acc[j][1] + bias_s[c + 1]);
        float h2 = sp(acc[j][2] + bias_s[c]);
        float h3 = sp(acc[j][3] + bias_s[c + 1]);
        int kk = j >> 1, half = (j & 1) << 1;
        ahi[kk][half]     = pack_h2(h0, h1);
        ahi[kk][half + 1] = pack_h2(h2, h3);
    }
}

// ---------------- prep: transpose + split weights into g_wt ----------------
__global__ void prep_kernel(const float* __restrict__ W1, const float* __restrict__ W2,
                            const float* __restrict__ W3) {
    int tid = blockIdx.x * blockDim.x + threadIdx.x;
    int stride = gridDim.x * blockDim.x;
    // w1/w2 slots: o = n*WSTR + k, valid k<128
    for (int o = tid; o < 128 * WSTR; o += stride) {
        int n = o / WSTR, k = o % WSTR;
        float f1 = 0.f, f2 = 0.f;
        if (k < 128) { f1 = W1[k * 128 + n]; f2 = W2[k * 128 + n]; }
        __half h1 = __float2half_rn(f1);
        __half h2 = __float2half_rn(f2);
        g_wt.w1h[o] = h1; g_wt.w1l[o] = __float2half_rn(f1 - __half2float(h1));
        g_wt.w2h[o] = h2; g_wt.w2l[o] = __float2half_rn(f2 - __half2float(h2));
    }
    for (int o = tid; o < 64 * WSTR; o += stride) {
        int n = o / WSTR, k = o % WSTR;
        float f = (n < 59 && k < 128) ? W3[k * 59 + n] : 0.f;
        __half hh = __float2half_rn(f);
        g_wt.w3h[o] = hh; g_wt.w3l[o] = __float2half_rn(f - __half2float(hh));
    }
}

// ---------------- main kernel ----------------
__global__ void __launch_bounds__(384, 1)
skin_mma_kernel(const float* __restrict__ xyz,  const float* __restrict__ quats,
                const float* __restrict__ tfs,  const float* __restrict__ aabb_min,
                const float* __restrict__ aabb_max,
                const float* __restrict__ W0, const float* __restrict__ b0,
                const float* __restrict__ b1, const float* __restrict__ b2,
                const float* __restrict__ b3,
                float* __restrict__ out, int Npts, int ntiles)
{
    extern __shared__ char smem[];
    const int tid  = threadIdx.x;
    const int wid  = tid >> 5;
    const int lane = tid & 31;

    // stage weight blob
    {
        const uint4* src = (const uint4*)&g_wt;
        uint4* dst = (uint4*)smem;
        for (int i = tid; i < (int)(sizeof(WBlob) / 16); i += 384) dst[i] = src[i];
    }
    float* w0s  = (float*)(smem + OFF_W0);
    float* b0s  = (float*)(smem + OFF_B0);
    float* b1s  = (float*)(smem + OFF_B1);
    float* b2s  = (float*)(smem + OFF_B2);
    float* b3s  = (float*)(smem + OFF_B3);
    float* tfs_s = (float*)(smem + OFF_TFS);
    for (int i = tid; i < 3 * H; i += 384) w0s[i] = W0[i];
    if (tid < H) { b0s[tid] = b0[tid]; b1s[tid] = b1[tid]; b2s[tid] = b2[tid]; }
    if (tid < 64) b3s[tid] = (tid < 59) ? b3[tid] : 0.0f;
    for (int i = tid; i < NB * 16; i += 384) tfs_s[i] = tfs[i];
    __syncthreads();

    const uint32_t u_w1h = smem_u32(smem + OFF_W1H), u_w1l = smem_u32(smem + OFF_W1L);
    const uint32_t u_w2h = smem_u32(smem + OFF_W2H), u_w2l = smem_u32(smem + OFF_W2L);
    const uint32_t u_w3h = smem_u32(smem + OFF_W3H), u_w3l = smem_u32(smem + OFF_W3L);
    float* es_w = (float*)(smem + OFF_ES) + wid * (16 * ESTR);

    const float amn0 = __ldg(aabb_min + 0), amn1 = __ldg(aabb_min + 1), amn2 = __ldg(aabb_min + 2);
    const float amx0 = __ldg(aabb_max + 0), amx1 = __ldg(aabb_max + 1), amx2 = __ldg(aabb_max + 2);
    const float sc0 = 2.0f / (amx0 - amn0), sc1 = 2.0f / (amx1 - amn1), sc2 = 2.0f / (amx2 - amn2);

    const int g = lane >> 2;          // row group 0..7
    const int cbase = 2 * (lane & 3);

    for (int t = blockIdx.x; t < ntiles; t += gridDim.x) {
        const int pbase = t * TILE + wid * 16;

        uint32_t ahi[8][4];
        float acc[16][4];

        // ---- layer 0: 3 -> 128 fp32, pack to fp16 A frags ----
        {
            int pA = pbase + g;     if (pA >= Npts) pA = Npts - 1;
            int pB = pbase + g + 8; if (pB >= Npts) pB = Npts - 1;
            float xA0 = (xyz[(size_t)pA * 3 + 0] - amn0) * sc0 - 1.0f;
            float xA1 = (xyz[(size_t)pA * 3 + 1] - amn1) * sc1 - 1.0f;
            float xA2 = (xyz[(size_t)pA * 3 + 2] - amn2) * sc2 - 1.0f;
            float xB0 = (xyz[(size_t)pB * 3 + 0] - amn0) * sc0 - 1.0f;
            float xB1 = (xyz[(size_t)pB * 3 + 1] - amn1) * sc1 - 1.0f;
            float xB2 = (xyz[(size_t)pB * 3 + 2] - amn2) * sc2 - 1.0f;
            #pragma unroll
            for (int j = 0; j < 16; ++j) {
                int c = 8 * j + cbase;
                float w0c = w0s[c],     w1c = w0s[128 + c],     w2c = w0s[256 + c];
                float w0d = w0s[c + 1], w1d = w0s[128 + c + 1], w2d = w0s[256 + c + 1];
                float h0 = sp(b0s[c]     + xA0 * w0c + xA1 * w1c + xA2 * w2c);
                float h1 = sp(b0s[c + 1] + xA0 * w0d + xA1 * w1d + xA2 * w2d);
                float h2 = sp(b0s[c]     + xB0 * w0c + xB1 * w1c + xB2 * w2c);
                float h3 = sp(b0s[c + 1] + xB0 * w0d + xB1 * w1d + xB2 * w2d);
                int kk = j >> 1, half = (j & 1) << 1;
                ahi[kk][half]     = pack_h2(h0, h1);
                ahi[kk][half + 1] = pack_h2(h2, h3);
            }
        }

        // ---- layers 1, 2 ----
        gemm_layer<16>(acc, ahi, u_w1h, u_w1l, lane);
        act_pack(acc, b1s, ahi, lane);
        gemm_layer<16>(acc, ahi, u_w2h, u_w2l, lane);
        act_pack(acc, b2s, ahi, lane);

        // ---- layer 3: N=64 ----
        gemm_layer<8>(acc, ahi, u_w3h, u_w3l, lane);

        // stage logits to smem (guard col < 59; stride ESTR)
        __syncwarp();
        #pragma unroll
        for (int j = 0; j < 8; ++j) {
            int c = 8 * j + cbase;
            if (c < 59) {
                es_w[g * ESTR + c]       = acc[j][0] + b3s[c];
                es_w[(g + 8) * ESTR + c] = acc[j][2] + b3s[c];
            }
            if (c + 1 < 59) {
                es_w[g * ESTR + c + 1]       = acc[j][1] + b3s[c + 1];
                es_w[(g + 8) * ESTR + c + 1] = acc[j][3] + b3s[c + 1];
            }
        }
        __syncwarp();

        // ---- epilogue: lanes 0..15, one point each (x read lazily from smem) ----
        const int pg = pbase + lane;
        if (lane < 16 && pg < Npts) {
            const float* xr = es_w + lane * ESTR;
#define XV(i) xr[i]
            float P[NB];
            {
                float s0 = sigf(XV(0));
                float o1, o2, o3;
                sm3(XV(1), XV(2), XV(3), o1, o2, o3);
                P[1] = s0 * o1; P[2] = s0 * o2; P[3] = s0 * o3;
                P[0] = 1.0f - s0;
            }
#define BR(par, ch) { float a_ = P[par]; float s_ = sigf(XV(ch)); \
                      P[ch] = a_ * s_; P[par] = a_ * (1.0f - s_); }
#define SUB3(par, gate, c1, c2, c3) { float a_ = P[par]; float g_ = sigf(XV(gate)); \
        float o1_, o2_, o3_; sm3(XV(c1), XV(c2), XV(c3), o1_, o2_, o3_); \
        P[c1] = a_ * g_ * o1_; P[c2] = a_ * g_ * o2_; P[c3] = a_ * g_ * o3_; \
        P[par] = a_ * (1.0f - g_); }
#define SUB5(par, gate, c1, c2, c3, c4, c5) { float a_ = P[par]; float g_ = sigf(XV(gate)); \
        float o1_, o2_, o3_, o4_, o5_; sm5(XV(c1), XV(c2), XV(c3), XV(c4), XV(c5), o1_, o2_, o3_, o4_, o5_); \
        P[c1] = a_ * g_ * o1_; P[c2] = a_ * g_ * o2_; P[c3] = a_ * g_ * o3_; \
        P[c4] = a_ * g_ * o4_; P[c5] = a_ * g_ * o5_; P[par] = a_ * (1.0f - g_); }

            BR(1, 4)  BR(2, 5)  BR(3, 6)
            BR(4, 7)  BR(5, 8)  BR(6, 9)
            BR(7, 10) BR(8, 11)
            SUB3(9, 55, 12, 13, 14)
            BR(12, 15)
            BR(13, 16) BR(14, 17)
            BR(16, 18) BR(17, 19)
            BR(18, 20) BR(19, 21)
            SUB3(15, 56, 22, 23, 24)
            SUB5(20, 57, 25, 28, 31, 34, 37)
            SUB5(21, 58, 40, 43, 46, 49, 52)
            BR(25, 26) BR(28, 29) BR(31, 32) BR(34, 35) BR(37, 38)
            BR(26, 27) BR(29, 30) BR(32, 33) BR(35, 36) BR(38, 39)
            BR(40, 41) BR(43, 44) BR(46, 47) BR(49, 50) BR(52, 53)
            BR(41, 42) BR(44, 45) BR(47, 48) BR(50, 51) BR(53, 54)
#undef BR
#undef SUB3
#undef SUB5
#undef XV

            float T[16];
            #pragma unroll
            for (int q = 0; q < 16; ++q) T[q] = 0.0f;
            #pragma unroll
            for (int b = 0; b < NB; ++b) {
                float w = P[b];
                #pragma unroll
                for (int q = 0; q < 16; ++q) T[q] += w * tfs_s[b * 16 + q];
            }

            float X = xyz[(size_t)pg * 3 + 0];
            float Y = xyz[(size_t)pg * 3 + 1];
            float Z = xyz[(size_t)pg * 3 + 2];
            float xb0 = T[0] * X + T[1] * Y + T[2]  * Z + T[3];
            float xb1 = T[4] * X + T[5] * Y + T[6]  * Z + T[7];
            float xb2 = T[8] * X + T[9] * Y + T[10] * Z + T[11];

            float4 qv = *(const float4*)(quats + (size_t)pg * 4);
            {
                float inv = rsqrtf(qv.x * qv.x + qv.y * qv.y + qv.z * qv.z + qv.w * qv.w);
                qv.x *= inv; qv.y *= inv; qv.z *= inv; qv.w *= inv;
            }
            float r = qv.x, xq = qv.y, yq = qv.z, zq = qv.w;
            float R[3][3];
            R[0][0] = 1.0f - 2.0f * (yq * yq + zq * zq);
            R[0][1] = 2.0f * (xq * yq - r * zq);
            R[0][2] = 2.0f * (xq * zq + r * yq);
            R[1][0] = 2.0f * (xq * yq + r * zq);
            R[1][1] = 1.0f - 2.0f * (xq * xq + zq * zq);
            R[1][2] = 2.0f * (yq * zq - r * xq);
            R[2][0] = 2.0f * (xq * zq - r * yq);
            R[2][1] = 2.0f * (yq * zq + r * xq);
            R[2][2] = 1.0f - 2.0f * (xq * xq + yq * yq);

            float rb[3][3];
            #pragma unroll
            for (int i = 0; i < 3; ++i)
                #pragma unroll
                for (int k = 0; k < 3; ++k)
                    rb[i][k] = T[i * 4 + 0] * R[0][k] + T[i * 4 + 1] * R[1][k] + T[i * 4 + 2] * R[2][k];

            float m00 = rb[0][0], m01 = rb[0][1], m02 = rb[0][2];
            float m10 = rb[1][0], m11 = rb[1][1], m12 = rb[1][2];
            float m20 = rb[2][0], m21 = rb[2][1], m22 = rb[2][2];
            float t0 = 1.0f + m00 + m11 + m22;
            float t1 = 1.0f + m00 - m11 - m22;
            float t2 = 1.0f - m00 + m11 - m22;
            float t3 = 1.0f - m00 - m11 + m22;

            int best = 0; float tb = t0;
            if (t1 > tb) { best = 1; tb = t1; }
            if (t2 > tb) { best = 2; tb = t2; }
            if (t3 > tb) { best = 3; tb = t3; }

            float qa, qb2, qc, qd;
            if (best == 0)      { qa = t0;        qb2 = m21 - m12; qc = m02 - m20; qd = m10 - m01; }
            else if (best == 1) { qa = m21 - m12; qb2 = t1;        qc = m01 + m10; qd = m02 + m20; }
            else if (best == 2) { qa = m02 - m20; qb2 = m01 + m10; qc = t2;        qd = m12 + m21; }
            else                { qa = m10 - m01; qb2 = m02 + m20; qc = m12 + m21; qd = t3;        }
            float scale = 0.5f * rsqrtf(fmaxf(tb, 1e-8f));
            qa *= scale; qb2 *= scale; qc *= scale; qd *= scale;
            float qinv = rsqrtf(qa * qa + qb2 * qb2 + qc * qc + qd * qd);
            qa *= qinv; qb2 *= qinv; qc *= qinv; qd *= qinv;

            const size_t n = (size_t)Npts;
            out[(size_t)pg * 3 + 0] = xb0;
            out[(size_t)pg * 3 + 1] = xb1;
            out[(size_t)pg * 3 + 2] = xb2;
            float* ro = out + 3 * n + (size_t)pg * 9;
            #pragma unroll
            for (int i = 0; i < 3; ++i)
                #pragma unroll
                for (int k = 0; k < 3; ++k) ro[i * 3 + k] = rb[i][k];
            float* qo = out + 12 * n + (size_t)pg * 4;
            qo[0] = qa; qo[1] = qb2; qo[2] = qc; qo[3] = qd;
            float* to = out + 16 * n + (size_t)pg * 16;
            #pragma unroll
            for (int q = 0; q < 16; ++q) to[q] = T[q];
        }
        __syncwarp();
    }
}

extern "C" void kernel_launch(void* const* d_in, const int* in_sizes, int n_in,
                              void* d_out, int out_size)
{
    const float* xyz      = (const float*)d_in[0];
    const float* quats    = (const float*)d_in[1];
    const float* tfs      = (const float*)d_in[2];
    const float* aabb_min = (const float*)d_in[3];
    const float* aabb_max = (const float*)d_in[4];
    const float* W0 = (const float*)d_in[5];
    const float* b0 = (const float*)d_in[6];
    const float* W1 = (const float*)d_in[7];
    const float* b1 = (const float*)d_in[8];
    const float* W2 = (const float*)d_in[9];
    const float* b2 = (const float*)d_in[10];
    const float* W3 = (const float*)d_in[11];
    const float* b3 = (const float*)d_in[12];
    float* out = (float*)d_out;

    int Npts = in_sizes[0] / 3;
    int ntiles = (Npts + TILE - 1) / TILE;

    int sms = 0;
    cudaDeviceGetAttribute(&sms, cudaDevAttrMultiProcessorCount, 0);
    if (sms <= 0) sms = 148;
    int grid = (sms < ntiles) ? sms : ntiles;

    prep_kernel<<<64, 256>>>(W1, W2, W3);

    cudaFuncSetAttribute(skin_mma_kernel,
                         cudaFuncAttributeMaxDynamicSharedMemorySize, SMEM_TOTAL);
    skin_mma_kernel<<<grid, 384, SMEM_TOTAL>>>(
        xyz, quats, tfs, aabb_min, aabb_max,
        W0, b0, b1, b2, b3, out, Npts, ntiles);
}

// round 5
// speedup vs baseline: 4.8057x; 1.2013x over previous
#include <cuda_runtime.h>
#include <cuda_fp16.h>
#include <stdint.h>

// SkinningField R5: single-pass fp16 mma.sync (no B split), 384 threads,
// TILE=192, register-resident activations, persistent CTAs.

#define H    128
#define NB   55
#define TILE 192          // 12 warps x 16 points
#define NWARP 12
#define WSTR 136          // padded weight row stride (fp16 elems)
#define ESTR 61           // epilogue staging row stride (floats)

// smem byte offsets
#define OFF_W1  0
#define OFF_W2  34816
#define OFF_W3  69632
#define OFF_W0  87040                  // 384 floats
#define OFF_B0  (OFF_W0 + 1536)
#define OFF_B1  (OFF_B0 + 512)
#define OFF_B2  (OFF_B1 + 512)
#define OFF_B3  (OFF_B2 + 512)        // 64 floats
#define OFF_TFS (OFF_B3 + 256)        // 880 floats
#define OFF_ES  (OFF_TFS + 3520)
#define SMEM_TOTAL (OFF_ES + NWARP * 16 * ESTR * 4)   // ~140 KB

struct __align__(16) WBlob {
    __half w1[128 * WSTR];
    __half w2[128 * WSTR];
    __half w3[64 * WSTR];
};
__device__ WBlob g_wt;

// ---------------- helpers ----------------
__device__ __forceinline__ uint32_t smem_u32(const void* p) {
    uint32_t a;
    asm("{ .reg .u64 t; cvta.to.shared.u64 t, %1; cvt.u32.u64 %0, t; }" : "=r"(a) : "l"(p));
    return a;
}
__device__ __forceinline__ float sigf(float v) { return 1.0f / (1.0f + __expf(-v)); }
__device__ __forceinline__ float sp(float v) {
    return fmaxf(v, 0.0f) + __logf(1.0f + __expf(-fabsf(v)));
}
__device__ __forceinline__ void sm3(float a, float b, float c, float& oa, float& ob, float& oc) {
    float m = fmaxf(a, fmaxf(b, c));
    float ea = __expf(a - m), eb = __expf(b - m), ec = __expf(c - m);
    float inv = 1.0f / (ea + eb + ec);
    oa = ea * inv; ob = eb * inv; oc = ec * inv;
}
__device__ __forceinline__ void sm5(float a, float b, float c, float d, float e,
                                    float& oa, float& ob, float& oc, float& od, float& oe) {
    float m = fmaxf(fmaxf(a, b), fmaxf(fmaxf(c, d), e));
    float ea = __expf(a - m), eb = __expf(b - m), ec = __expf(c - m),
          ed = __expf(d - m), ee = __expf(e - m);
    float inv = 1.0f / (ea + eb + ec + ed + ee);
    oa = ea * inv; ob = eb * inv; oc = ec * inv; od = ed * inv; oe = ee * inv;
}
__device__ __forceinline__ uint32_t pack_h2(float h0, float h1) {
    uint32_t w;
    asm("cvt.rn.f16x2.f32 %0, %1, %2;" : "=r"(w) : "f"(h1), "f"(h0));
    return w;
}

__device__ __forceinline__ void mma_f16(float& d0, float& d1, float& d2, float& d3,
                                        uint32_t a0, uint32_t a1, uint32_t a2, uint32_t a3,
                                        uint32_t b0, uint32_t b1) {
    asm volatile("mma.sync.aligned.m16n8k16.row.col.f32.f16.f16.f32 "
                 "{%0,%1,%2,%3}, {%4,%5,%6,%7}, {%8,%9}, {%0,%1,%2,%3};"
                 : "+f"(d0), "+f"(d1), "+f"(d2), "+f"(d3)
                 : "r"(a0), "r"(a1), "r"(a2), "r"(a3), "r"(b0), "r"(b1));
}

// ldmatrix x4: {b0,b1} = B-frag n-chunk n0/8, {b2,b3} = n-chunk n0/8+1
__device__ __forceinline__ void ldx4(uint32_t b[4], uint32_t base, int lane, int n0, int k0) {
    int grp = lane >> 3, r = lane & 7;
    int row = n0 + r + ((grp >> 1) << 3);
    int col = k0 + ((grp & 1) << 3);
    uint32_t addr = base + (uint32_t)(row * WSTR + col) * 2u;
    asm volatile("ldmatrix.sync.aligned.m8n8.x4.shared.b16 {%0,%1,%2,%3}, [%4];"
                 : "=r"(b[0]), "=r"(b[1]), "=r"(b[2]), "=r"(b[3]) : "r"(addr));
}

// single-pass fp16 GEMM: D = A*B
template <int NC>
__device__ __forceinline__ void gemm_layer(float acc[][4], const uint32_t ahi[8][4],
                                           uint32_t wsm, int lane) {
    #pragma unroll
    for (int j = 0; j < NC; ++j) { acc[j][0] = 0.f; acc[j][1] = 0.f; acc[j][2] = 0.f; acc[j][3] = 0.f; }
    #pragma unroll
    for (int kk = 0; kk < 8; ++kk) {
        #pragma unroll
        for (int jj = 0; jj < NC / 2; ++jj) {
            uint32_t bh[4];
            ldx4(bh, wsm, lane, 16 * jj, 16 * kk);
            float* aL = acc[2 * jj];
            float* aR = acc[2 * jj + 1];
            mma_f16(aL[0], aL[1], aL[2], aL[3], ahi[kk][0], ahi[kk][1], ahi[kk][2], ahi[kk][3], bh[0], bh[1]);
            mma_f16(aR[0], aR[1], aR[2], aR[3], ahi[kk][0], ahi[kk][1], ahi[kk][2], ahi[kk][3], bh[2], bh[3]);
        }
    }
}

// bias + softplus + fp16 pack: acc(16 chunks) -> next-layer A frags
__device__ __forceinline__ void act_pack(const float acc[][4], const float* bias_s,
                                         uint32_t ahi[8][4], int lane) {
    const int cbase = 2 * (lane & 3);
    #pragma unroll
    for (int j = 0; j < 16; ++j) {
        int c = 8 * j + cbase;
        float h0 = sp(acc[j][0] + bias_s[c]);
        float h1 = sp(acc[j][1] + bias_s[c + 1]);
        float h2 = sp(acc[j][2] + bias_s[c]);
        float h3 = sp(acc[j][3] + bias_s[c + 1]);
        int kk = j >> 1, half = (j & 1) << 1;
        ahi[kk][half]     = pack_h2(h0, h1);
        ahi[kk][half + 1] = pack_h2(h2, h3);
    }
}

// ---------------- prep: transpose weights into g_wt ----------------
__global__ void prep_kernel(const float* __restrict__ W1, const float* __restrict__ W2,
                            const float* __restrict__ W3) {
    int tid = blockIdx.x * blockDim.x + threadIdx.x;
    int stride = gridDim.x * blockDim.x;
    for (int o = tid; o < 128 * WSTR; o += stride) {
        int n = o / WSTR, k = o % WSTR;
        float f1 = 0.f, f2 = 0.f;
        if (k < 128) { f1 = W1[k * 128 + n]; f2 = W2[k * 128 + n]; }
        g_wt.w1[o] = __float2half_rn(f1);
        g_wt.w2[o] = __float2half_rn(f2);
    }
    for (int o = tid; o < 64 * WSTR; o += stride) {
        int n = o / WSTR, k = o % WSTR;
        float f = (n < 59 && k < 128) ? W3[k * 59 + n] : 0.f;
        g_wt.w3[o] = __float2half_rn(f);
    }
}

// ---------------- main kernel ----------------
__global__ void __launch_bounds__(384, 1)
skin_mma_kernel(const float* __restrict__ xyz,  const float* __restrict__ quats,
                const float* __restrict__ tfs,  const float* __restrict__ aabb_min,
                const float* __restrict__ aabb_max,
                const float* __restrict__ W0, const float* __restrict__ b0,
                const float* __restrict__ b1, const float* __restrict__ b2,
                const float* __restrict__ b3,
                float* __restrict__ out, int Npts, int ntiles)
{
    extern __shared__ char smem[];
    const int tid  = threadIdx.x;
    const int wid  = tid >> 5;
    const int lane = tid & 31;

    // stage weight blob
    {
        const uint4* src = (const uint4*)&g_wt;
        uint4* dst = (uint4*)smem;
        for (int i = tid; i < (int)(sizeof(WBlob) / 16); i += 384) dst[i] = src[i];
    }
    float* w0s  = (float*)(smem + OFF_W0);
    float* b0s  = (float*)(smem + OFF_B0);
    float* b1s  = (float*)(smem + OFF_B1);
    float* b2s  = (float*)(smem + OFF_B2);
    float* b3s  = (float*)(smem + OFF_B3);
    float* tfs_s = (float*)(smem + OFF_TFS);
    for (int i = tid; i < 3 * H; i += 384) w0s[i] = W0[i];
    if (tid < H) { b0s[tid] = b0[tid]; b1s[tid] = b1[tid]; b2s[tid] = b2[tid]; }
    if (tid < 64) b3s[tid] = (tid < 59) ? b3[tid] : 0.0f;
    for (int i = tid; i < NB * 16; i += 384) tfs_s[i] = tfs[i];
    __syncthreads();

    const uint32_t u_w1 = smem_u32(smem + OFF_W1);
    const uint32_t u_w2 = smem_u32(smem + OFF_W2);
    const uint32_t u_w3 = smem_u32(smem + OFF_W3);
    float* es_w = (float*)(smem + OFF_ES) + wid * (16 * ESTR);

    const float amn0 = __ldg(aabb_min + 0), amn1 = __ldg(aabb_min + 1), amn2 = __ldg(aabb_min + 2);
    const float amx0 = __ldg(aabb_max + 0), amx1 = __ldg(aabb_max + 1), amx2 = __ldg(aabb_max + 2);
    const float sc0 = 2.0f / (amx0 - amn0), sc1 = 2.0f / (amx1 - amn1), sc2 = 2.0f / (amx2 - amn2);

    const int g = lane >> 2;          // row group 0..7
    const int cbase = 2 * (lane & 3);

    for (int t = blockIdx.x; t < ntiles; t += gridDim.x) {
        const int pbase = t * TILE + wid * 16;

        uint32_t ahi[8][4];
        float acc[16][4];

        // ---- layer 0: 3 -> 128 fp32, pack to fp16 A frags ----
        {
            int pA = pbase + g;     if (pA >= Npts) pA = Npts - 1;
            int pB = pbase + g + 8; if (pB >= Npts) pB = Npts - 1;
            float xA0 = (xyz[(size_t)pA * 3 + 0] - amn0) * sc0 - 1.0f;
            float xA1 = (xyz[(size_t)pA * 3 + 1] - amn1) * sc1 - 1.0f;
            float xA2 = (xyz[(size_t)pA * 3 + 2] - amn2) * sc2 - 1.0f;
            float xB0 = (xyz[(size_t)pB * 3 + 0] - amn0) * sc0 - 1.0f;
            float xB1 = (xyz[(size_t)pB * 3 + 1] - amn1) * sc1 - 1.0f;
            float xB2 = (xyz[(size_t)pB * 3 + 2] - amn2) * sc2 - 1.0f;
            #pragma unroll
            for (int j = 0; j < 16; ++j) {
                int c = 8 * j + cbase;
                float w0c = w0s[c],     w1c = w0s[128 + c],     w2c = w0s[256 + c];
                float w0d = w0s[c + 1], w1d = w0s[128 + c + 1], w2d = w0s[256 + c + 1];
                float h0 = sp(b0s[c]     + xA0 * w0c + xA1 * w1c + xA2 * w2c);
                float h1 = sp(b0s[c + 1] + xA0 * w0d + xA1 * w1d + xA2 * w2d);
                float h2 = sp(b0s[c]     + xB0 * w0c + xB1 * w1c + xB2 * w2c);
                float h3 = sp(b0s[c + 1] + xB0 * w0d + xB1 * w1d + xB2 * w2d);
                int kk = j >> 1, half = (j & 1) << 1;
                ahi[kk][half]     = pack_h2(h0, h1);
                ahi[kk][half + 1] = pack_h2(h2, h3);
            }
        }

        // ---- layers 1, 2 ----
        gemm_layer<16>(acc, ahi, u_w1, lane);
        act_pack(acc, b1s, ahi, lane);
        gemm_layer<16>(acc, ahi, u_w2, lane);
        act_pack(acc, b2s, ahi, lane);

        // ---- layer 3: N=64 ----
        gemm_layer<8>(acc, ahi, u_w3, lane);

        // stage logits to smem (guard col < 59)
        __syncwarp();
        #pragma unroll
        for (int j = 0; j < 8; ++j) {
            int c = 8 * j + cbase;
            if (c < 59) {
                es_w[g * ESTR + c]       = acc[j][0] + b3s[c];
                es_w[(g + 8) * ESTR + c] = acc[j][2] + b3s[c];
            }
            if (c + 1 < 59) {
                es_w[g * ESTR + c + 1]       = acc[j][1] + b3s[c + 1];
                es_w[(g + 8) * ESTR + c + 1] = acc[j][3] + b3s[c + 1];
            }
        }
        __syncwarp();

        // ---- epilogue: lanes 0..15, one point each ----
        const int pg = pbase + lane;
        if (lane < 16 && pg < Npts) {
            const float* xr = es_w + lane * ESTR;
#define XV(i) xr[i]
            float P[NB];
            {
                float s0 = sigf(XV(0));
                float o1, o2, o3;
                sm3(XV(1), XV(2), XV(3), o1, o2, o3);
                P[1] = s0 * o1; P[2] = s0 * o2; P[3] = s0 * o3;
                P[0] = 1.0f - s0;
            }
#define BR(par, ch) { float a_ = P[par]; float s_ = sigf(XV(ch)); \
                      P[ch] = a_ * s_; P[par] = a_ * (1.0f - s_); }
#define SUB3(par, gate, c1, c2, c3) { float a_ = P[par]; float g_ = sigf(XV(gate)); \
        float o1_, o2_, o3_; sm3(XV(c1), XV(c2), XV(c3), o1_, o2_, o3_); \
        P[c1] = a_ * g_ * o1_; P[c2] = a_ * g_ * o2_; P[c3] = a_ * g_ * o3_; \
        P[par] = a_ * (1.0f - g_); }
#define SUB5(par, gate, c1, c2, c3, c4, c5) { float a_ = P[par]; float g_ = sigf(XV(gate)); \
        float o1_, o2_, o3_, o4_, o5_; sm5(XV(c1), XV(c2), XV(c3), XV(c4), XV(c5), o1_, o2_, o3_, o4_, o5_); \
        P[c1] = a_ * g_ * o1_; P[c2] = a_ * g_ * o2_; P[c3] = a_ * g_ * o3_; \
        P[c4] = a_ * g_ * o4_; P[c5] = a_ * g_ * o5_; P[par] = a_ * (1.0f - g_); }

            BR(1, 4)  BR(2, 5)  BR(3, 6)
            BR(4, 7)  BR(5, 8)  BR(6, 9)
            BR(7, 10) BR(8, 11)
            SUB3(9, 55, 12, 13, 14)
            BR(12, 15)
            BR(13, 16) BR(14, 17)
            BR(16, 18) BR(17, 19)
            BR(18, 20) BR(19, 21)
            SUB3(15, 56, 22, 23, 24)
            SUB5(20, 57, 25, 28, 31, 34, 37)
            SUB5(21, 58, 40, 43, 46, 49, 52)
            BR(25, 26) BR(28, 29) BR(31, 32) BR(34, 35) BR(37, 38)
            BR(26, 27) BR(29, 30) BR(32, 33) BR(35, 36) BR(38, 39)
            BR(40, 41) BR(43, 44) BR(46, 47) BR(49, 50) BR(52, 53)
            BR(41, 42) BR(44, 45) BR(47, 48) BR(50, 51) BR(53, 54)
#undef BR
#undef SUB3
#undef SUB5
#undef XV

            float T[16];
            #pragma unroll
            for (int q = 0; q < 16; ++q) T[q] = 0.0f;
            #pragma unroll
            for (int b = 0; b < NB; ++b) {
                float w = P[b];
                #pragma unroll
                for (int q = 0; q < 16; ++q) T[q] += w * tfs_s[b * 16 + q];
            }

            float X = xyz[(size_t)pg * 3 + 0];
            float Y = xyz[(size_t)pg * 3 + 1];
            float Z = xyz[(size_t)pg * 3 + 2];
            float xb0 = T[0] * X + T[1] * Y + T[2]  * Z + T[3];
            float xb1 = T[4] * X + T[5] * Y + T[6]  * Z + T[7];
            float xb2 = T[8] * X + T[9] * Y + T[10] * Z + T[11];

            float4 qv = *(const float4*)(quats + (size_t)pg * 4);
            {
                float inv = rsqrtf(qv.x * qv.x + qv.y * qv.y + qv.z * qv.z + qv.w * qv.w);
                qv.x *= inv; qv.y *= inv; qv.z *= inv; qv.w *= inv;
            }
            float r = qv.x, xq = qv.y, yq = qv.z, zq = qv.w;
            float R[3][3];
            R[0][0] = 1.0f - 2.0f * (yq * yq + zq * zq);
            R[0][1] = 2.0f * (xq * yq - r * zq);
            R[0][2] = 2.0f * (xq * zq + r * yq);
            R[1][0] = 2.0f * (xq * yq + r * zq);
            R[1][1] = 1.0f - 2.0f * (xq * xq + zq * zq);
            R[1][2] = 2.0f * (yq * zq - r * xq);
            R[2][0] = 2.0f * (xq * zq - r * yq);
            R[2][1] = 2.0f * (yq * zq + r * xq);
            R[2][2] = 1.0f - 2.0f * (xq * xq + yq * yq);

            float rb[3][3];
            #pragma unroll
            for (int i = 0; i < 3; ++i)
                #pragma unroll
                for (int k = 0; k < 3; ++k)
                    rb[i][k] = T[i * 4 + 0] * R[0][k] + T[i * 4 + 1] * R[1][k] + T[i * 4 + 2] * R[2][k];

            float m00 = rb[0][0], m01 = rb[0][1], m02 = rb[0][2];
            float m10 = rb[1][0], m11 = rb[1][1], m12 = rb[1][2];
            float m20 = rb[2][0], m21 = rb[2][1], m22 = rb[2][2];
            float t0 = 1.0f + m00 + m11 + m22;
            float t1 = 1.0f + m00 - m11 - m22;
            float t2 = 1.0f - m00 + m11 - m22;
            float t3 = 1.0f - m00 - m11 + m22;

            int best = 0; float tb = t0;
            if (t1 > tb) { best = 1; tb = t1; }
            if (t2 > tb) { best = 2; tb = t2; }
            if (t3 > tb) { best = 3; tb = t3; }

            float qa, qb2, qc, qd;
            if (best == 0)      { qa = t0;        qb2 = m21 - m12; qc = m02 - m20; qd = m10 - m01; }
            else if (best == 1) { qa = m21 - m12; qb2 = t1;        qc = m01 + m10; qd = m02 + m20; }
            else if (best == 2) { qa = m02 - m20; qb2 = m01 + m10; qc = t2;        qd = m12 + m21; }
            else                { qa = m10 - m01; qb2 = m02 + m20; qc = m12 + m21; qd = t3;        }
            float scale = 0.5f * rsqrtf(fmaxf(tb, 1e-8f));
            qa *= scale; qb2 *= scale; qc *= scale; qd *= scale;
            float qinv = rsqrtf(qa * qa + qb2 * qb2 + qc * qc + qd * qd);
            qa *= qinv; qb2 *= qinv; qc *= qinv; qd *= qinv;

            const size_t n = (size_t)Npts;
            out[(size_t)pg * 3 + 0] = xb0;
            out[(size_t)pg * 3 + 1] = xb1;
            out[(size_t)pg * 3 + 2] = xb2;
            float* ro = out + 3 * n + (size_t)pg * 9;
            #pragma unroll
            for (int i = 0; i < 3; ++i)
                #pragma unroll
                for (int k = 0; k < 3; ++k) ro[i * 3 + k] = rb[i][k];
            float* qo = out + 12 * n + (size_t)pg * 4;
            qo[0] = qa; qo[1] = qb2; qo[2] = qc; qo[3] = qd;
            float* to = out + 16 * n + (size_t)pg * 16;
            #pragma unroll
            for (int q = 0; q < 16; ++q) to[q] = T[q];
        }
        __syncwarp();
    }
}

extern "C" void kernel_launch(void* const* d_in, const int* in_sizes, int n_in,
                              void* d_out, int out_size)
{
    const float* xyz      = (const float*)d_in[0];
    const float* quats    = (const float*)d_in[1];
    const float* tfs      = (const float*)d_in[2];
    const float* aabb_min = (const float*)d_in[3];
    const float* aabb_max = (const float*)d_in[4];
    const float* W0 = (const float*)d_in[5];
    const float* b0 = (const float*)d_in[6];
    const float* W1 = (const float*)d_in[7];
    const float* b1 = (const float*)d_in[8];
    const float* W2 = (const float*)d_in[9];
    const float* b2 = (const float*)d_in[10];
    const float* W3 = (const float*)d_in[11];
    const float* b3 = (const float*)d_in[12];
    float* out = (float*)d_out;

    int Npts = in_sizes[0] / 3;
    int ntiles = (Npts + TILE - 1) / TILE;

    int sms = 0;
    cudaDeviceGetAttribute(&sms, cudaDevAttrMultiProcessorCount, 0);
    if (sms <= 0) sms = 148;
    int grid = (sms < ntiles) ? sms : ntiles;

    prep_kernel<<<64, 256>>>(W1, W2, W3);

    cudaFuncSetAttribute(skin_mma_kernel,
                         cudaFuncAttributeMaxDynamicSharedMemorySize, SMEM_TOTAL);
    skin_mma_kernel<<<grid, 384, SMEM_TOTAL>>>(
        xyz, quats, tfs, aabb_min, aabb_max,
        W0, b0, b1, b2, b3, out, Npts, ntiles);
}

// round 7
// speedup vs baseline: 7.3265x; 1.5245x over previous
#include <cuda_runtime.h>
#include <cuda_fp16.h>
#include <stdint.h>

// SkinningField R6b (re-bench of R6 after infra failure): single-pass fp16
// mma.sync, 384 threads, TILE=384 (each warp: 32 points via two 16-point MLP
// passes), full-warp epilogue, __fdividef reciprocals.

#define H    128
#define NB   55
#define TILE 384          // 12 warps x 32 points
#define NWARP 12
#define WSTR 136          // padded weight row stride (fp16 elems)
#define ESTR 61           // epilogue staging row stride (floats)

// smem byte offsets
#define OFF_W1  0
#define OFF_W2  34816
#define OFF_W3  69632
#define OFF_W0  87040                  // 384 floats
#define OFF_B0  (OFF_W0 + 1536)
#define OFF_B1  (OFF_B0 + 512)
#define OFF_B2  (OFF_B1 + 512)
#define OFF_B3  (OFF_B2 + 512)        // 64 floats
#define OFF_TFS (OFF_B3 + 256)        // 880 floats
#define OFF_ES  (OFF_TFS + 3520)
#define SMEM_TOTAL (OFF_ES + NWARP * 32 * ESTR * 4)   // 187584

struct __align__(16) WBlob {
    __half w1[128 * WSTR];
    __half w2[128 * WSTR];
    __half w3[64 * WSTR];
};
__device__ WBlob g_wt;

// ---------------- helpers ----------------
__device__ __forceinline__ uint32_t smem_u32(const void* p) {
    uint32_t a;
    asm("{ .reg .u64 t; cvta.to.shared.u64 t, %1; cvt.u32.u64 %0, t; }" : "=r"(a) : "l"(p));
    return a;
}
__device__ __forceinline__ float sigf(float v) {
    return __fdividef(1.0f, 1.0f + __expf(-v));
}
__device__ __forceinline__ float sp(float v) {
    return fmaxf(v, 0.0f) + __logf(1.0f + __expf(-fabsf(v)));
}
__device__ __forceinline__ void sm3(float a, float b, float c, float& oa, float& ob, float& oc) {
    float m = fmaxf(a, fmaxf(b, c));
    float ea = __expf(a - m), eb = __expf(b - m), ec = __expf(c - m);
    float inv = __fdividef(1.0f, ea + eb + ec);
    oa = ea * inv; ob = eb * inv; oc = ec * inv;
}
__device__ __forceinline__ void sm5(float a, float b, float c, float d, float e,
                                    float& oa, float& ob, float& oc, float& od, float& oe) {
    float m = fmaxf(fmaxf(a, b), fmaxf(fmaxf(c, d), e));
    float ea = __expf(a - m), eb = __expf(b - m), ec = __expf(c - m),
          ed = __expf(d - m), ee = __expf(e - m);
    float inv = __fdividef(1.0f, ea + eb + ec + ed + ee);
    oa = ea * inv; ob = eb * inv; oc = ec * inv; od = ed * inv; oe = ee * inv;
}
__device__ __forceinline__ uint32_t pack_h2(float h0, float h1) {
    uint32_t w;
    asm("cvt.rn.f16x2.f32 %0, %1, %2;" : "=r"(w) : "f"(h1), "f"(h0));
    return w;
}

__device__ __forceinline__ void mma_f16(float& d0, float& d1, float& d2, float& d3,
                                        uint32_t a0, uint32_t a1, uint32_t a2, uint32_t a3,
                                        uint32_t b0, uint32_t b1) {
    asm volatile("mma.sync.aligned.m16n8k16.row.col.f32.f16.f16.f32 "
                 "{%0,%1,%2,%3}, {%4,%5,%6,%7}, {%8,%9}, {%0,%1,%2,%3};"
                 : "+f"(d0), "+f"(d1), "+f"(d2), "+f"(d3)
                 : "r"(a0), "r"(a1), "r"(a2), "r"(a3), "r"(b0), "r"(b1));
}

__device__ __forceinline__ void ldx4(uint32_t b[4], uint32_t base, int lane, int n0, int k0) {
    int grp = lane >> 3, r = lane & 7;
    int row = n0 + r + ((grp >> 1) << 3);
    int col = k0 + ((grp & 1) << 3);
    uint32_t addr = base + (uint32_t)(row * WSTR + col) * 2u;
    asm volatile("ldmatrix.sync.aligned.m8n8.x4.shared.b16 {%0,%1,%2,%3}, [%4];"
                 : "=r"(b[0]), "=r"(b[1]), "=r"(b[2]), "=r"(b[3]) : "r"(addr));
}

template <int NC>
__device__ __forceinline__ void gemm_layer(float acc[][4], const uint32_t ahi[8][4],
                                           uint32_t wsm, int lane) {
    #pragma unroll
    for (int j = 0; j < NC; ++j) { acc[j][0] = 0.f; acc[j][1] = 0.f; acc[j][2] = 0.f; acc[j][3] = 0.f; }
    #pragma unroll
    for (int kk = 0; kk < 8; ++kk) {
        #pragma unroll
        for (int jj = 0; jj < NC / 2; ++jj) {
            uint32_t bh[4];
            ldx4(bh, wsm, lane, 16 * jj, 16 * kk);
            float* aL = acc[2 * jj];
            float* aR = acc[2 * jj + 1];
            mma_f16(aL[0], aL[1], aL[2], aL[3], ahi[kk][0], ahi[kk][1], ahi[kk][2], ahi[kk][3], bh[0], bh[1]);
            mma_f16(aR[0], aR[1], aR[2], aR[3], ahi[kk][0], ahi[kk][1], ahi[kk][2], ahi[kk][3], bh[2], bh[3]);
        }
    }
}

__device__ __forceinline__ void act_pack(const float acc[][4], const float* bias_s,
                                         uint32_t ahi[8][4], int lane) {
    const int cbase = 2 * (lane & 3);
    #pragma unroll
    for (int j = 0; j < 16; ++j) {
        int c = 8 * j + cbase;
        float h0 = sp(acc[j][0] + bias_s[c]);
        float h1 = sp(acc[j][1] + bias_s[c + 1]);
        float h2 = sp(acc[j][2] + bias_s[c]);
        float h3 = sp(acc[j][3] + bias_s[c + 1]);
        int kk = j >> 1, half = (j & 1) << 1;
        ahi[kk][half]     = pack_h2(h0, h1);
        ahi[kk][half + 1] = pack_h2(h2, h3);
    }
}

// ---------------- prep: transpose weights into g_wt ----------------
__global__ void prep_kernel(const float* __restrict__ W1, const float* __restrict__ W2,
                            const float* __restrict__ W3) {
    int tid = blockIdx.x * blockDim.x + threadIdx.x;
    int stride = gridDim.x * blockDim.x;
    for (int o = tid; o < 128 * WSTR; o += stride) {
        int n = o / WSTR, k = o % WSTR;
        float f1 = 0.f, f2 = 0.f;
        if (k < 128) { f1 = W1[k * 128 + n]; f2 = W2[k * 128 + n]; }
        g_wt.w1[o] = __float2half_rn(f1);
        g_wt.w2[o] = __float2half_rn(f2);
    }
    for (int o = tid; o < 64 * WSTR; o += stride) {
        int n = o / WSTR, k = o % WSTR;
        float f = (n < 59 && k < 128) ? W3[k * 59 + n] : 0.f;
        g_wt.w3[o] = __float2half_rn(f);
    }
}

// ---------------- main kernel ----------------
__global__ void __launch_bounds__(384, 1)
skin_mma_kernel(const float* __restrict__ xyz,  const float* __restrict__ quats,
                const float* __restrict__ tfs,  const float* __restrict__ aabb_min,
                const float* __restrict__ aabb_max,
                const float* __restrict__ W0, const float* __restrict__ b0,
                const float* __restrict__ b1, const float* __restrict__ b2,
                const float* __restrict__ b3,
                float* __restrict__ out, int Npts, int ntiles)
{
    extern __shared__ char smem[];
    const int tid  = threadIdx.x;
    const int wid  = tid >> 5;
    const int lane = tid & 31;

    // stage weight blob
    {
        const uint4* src = (const uint4*)&g_wt;
        uint4* dst = (uint4*)smem;
        for (int i = tid; i < (int)(sizeof(WBlob) / 16); i += 384) dst[i] = src[i];
    }
    float* w0s  = (float*)(smem + OFF_W0);
    float* b0s  = (float*)(smem + OFF_B0);
    float* b1s  = (float*)(smem + OFF_B1);
    float* b2s  = (float*)(smem + OFF_B2);
    float* b3s  = (float*)(smem + OFF_B3);
    float* tfs_s = (float*)(smem + OFF_TFS);
    for (int i = tid; i < 3 * H; i += 384) w0s[i] = W0[i];
    if (tid < H) { b0s[tid] = b0[tid]; b1s[tid] = b1[tid]; b2s[tid] = b2[tid]; }
    if (tid < 64) b3s[tid] = (tid < 59) ? b3[tid] : 0.0f;
    for (int i = tid; i < NB * 16; i += 384) tfs_s[i] = tfs[i];
    __syncthreads();

    const uint32_t u_w1 = smem_u32(smem + OFF_W1);
    const uint32_t u_w2 = smem_u32(smem + OFF_W2);
    const uint32_t u_w3 = smem_u32(smem + OFF_W3);
    float* es_w = (float*)(smem + OFF_ES) + wid * (32 * ESTR);

    const float amn0 = __ldg(aabb_min + 0), amn1 = __ldg(aabb_min + 1), amn2 = __ldg(aabb_min + 2);
    const float amx0 = __ldg(aabb_max + 0), amx1 = __ldg(aabb_max + 1), amx2 = __ldg(aabb_max + 2);
    const float sc0 = 2.0f / (amx0 - amn0), sc1 = 2.0f / (amx1 - amn1), sc2 = 2.0f / (amx2 - amn2);

    const int g = lane >> 2;          // row group 0..7
    const int cbase = 2 * (lane & 3);

    for (int t = blockIdx.x; t < ntiles; t += gridDim.x) {
        const int pbase_w = t * TILE + wid * 32;

        // ---- two 16-point MLP passes per warp ----
        #pragma unroll
        for (int hf = 0; hf < 2; ++hf) {
            const int base16 = pbase_w + hf * 16;
            uint32_t ahi[8][4];
            float acc[16][4];

            // layer 0: 3 -> 128 fp32, pack to fp16 A frags
            {
                int pA = base16 + g;     if (pA >= Npts) pA = Npts - 1;
                int pB = base16 + g + 8; if (pB >= Npts) pB = Npts - 1;
                float xA0 = (xyz[(size_t)pA * 3 + 0] - amn0) * sc0 - 1.0f;
                float xA1 = (xyz[(size_t)pA * 3 + 1] - amn1) * sc1 - 1.0f;
                float xA2 = (xyz[(size_t)pA * 3 + 2] - amn2) * sc2 - 1.0f;
                float xB0 = (xyz[(size_t)pB * 3 + 0] - amn0) * sc0 - 1.0f;
                float xB1 = (xyz[(size_t)pB * 3 + 1] - amn1) * sc1 - 1.0f;
                float xB2 = (xyz[(size_t)pB * 3 + 2] - amn2) * sc2 - 1.0f;
                #pragma unroll
                for (int j = 0; j < 16; ++j) {
                    int c = 8 * j + cbase;
                    float w0c = w0s[c],     w1c = w0s[128 + c],     w2c = w0s[256 + c];
                    float w0d = w0s[c + 1], w1d = w0s[128 + c + 1], w2d = w0s[256 + c + 1];
                    float h0 = sp(b0s[c]     + xA0 * w0c + xA1 * w1c + xA2 * w2c);
                    float h1 = sp(b0s[c + 1] + xA0 * w0d + xA1 * w1d + xA2 * w2d);
                    float h2 = sp(b0s[c]     + xB0 * w0c + xB1 * w1c + xB2 * w2c);
                    float h3 = sp(b0s[c + 1] + xB0 * w0d + xB1 * w1d + xB2 * w2d);
                    int kk = j >> 1, half = (j & 1) << 1;
                    ahi[kk][half]     = pack_h2(h0, h1);
                    ahi[kk][half + 1] = pack_h2(h2, h3);
                }
            }

            gemm_layer<16>(acc, ahi, u_w1, lane);
            act_pack(acc, b1s, ahi, lane);
            gemm_layer<16>(acc, ahi, u_w2, lane);
            act_pack(acc, b2s, ahi, lane);
            gemm_layer<8>(acc, ahi, u_w3, lane);

            // stage logits (rows hf*16 + g / +8; guard col < 59)
            __syncwarp();
            #pragma unroll
            for (int j = 0; j < 8; ++j) {
                int c = 8 * j + cbase;
                int r0 = hf * 16 + g, r1 = r0 + 8;
                if (c < 59) {
                    es_w[r0 * ESTR + c] = acc[j][0] + b3s[c];
                    es_w[r1 * ESTR + c] = acc[j][2] + b3s[c];
                }
                if (c + 1 < 59) {
                    es_w[r0 * ESTR + c + 1] = acc[j][1] + b3s[c + 1];
                    es_w[r1 * ESTR + c + 1] = acc[j][3] + b3s[c + 1];
                }
            }
            __syncwarp();
        }

        // ---- epilogue: ALL 32 lanes, one point each ----
        const int pg = pbase_w + lane;
        if (pg < Npts) {
            const float* xr = es_w + lane * ESTR;
#define XV(i) xr[i]
            float P[NB];
            {
                float s0 = sigf(XV(0));
                float o1, o2, o3;
                sm3(XV(1), XV(2), XV(3), o1, o2, o3);
                P[1] = s0 * o1; P[2] = s0 * o2; P[3] = s0 * o3;
                P[0] = 1.0f - s0;
            }
#define BR(par, ch) { float a_ = P[par]; float s_ = sigf(XV(ch)); \
                      P[ch] = a_ * s_; P[par] = a_ * (1.0f - s_); }
#define SUB3(par, gate, c1, c2, c3) { float a_ = P[par]; float g_ = sigf(XV(gate)); \
        float o1_, o2_, o3_; sm3(XV(c1), XV(c2), XV(c3), o1_, o2_, o3_); \
        P[c1] = a_ * g_ * o1_; P[c2] = a_ * g_ * o2_; P[c3] = a_ * g_ * o3_; \
        P[par] = a_ * (1.0f - g_); }
#define SUB5(par, gate, c1, c2, c3, c4, c5) { float a_ = P[par]; float g_ = sigf(XV(gate)); \
        float o1_, o2_, o3_, o4_, o5_; sm5(XV(c1), XV(c2), XV(c3), XV(c4), XV(c5), o1_, o2_, o3_, o4_, o5_); \
        P[c1] = a_ * g_ * o1_; P[c2] = a_ * g_ * o2_; P[c3] = a_ * g_ * o3_; \
        P[c4] = a_ * g_ * o4_; P[c5] = a_ * g_ * o5_; P[par] = a_ * (1.0f - g_); }

            BR(1, 4)  BR(2, 5)  BR(3, 6)
            BR(4, 7)  BR(5, 8)  BR(6, 9)
            BR(7, 10) BR(8, 11)
            SUB3(9, 55, 12, 13, 14)
            BR(12, 15)
            BR(13, 16) BR(14, 17)
            BR(16, 18) BR(17, 19)
            BR(18, 20) BR(19, 21)
            SUB3(15, 56, 22, 23, 24)
            SUB5(20, 57, 25, 28, 31, 34, 37)
            SUB5(21, 58, 40, 43, 46, 49, 52)
            BR(25, 26) BR(28, 29) BR(31, 32) BR(34, 35) BR(37, 38)
            BR(26, 27) BR(29, 30) BR(32, 33) BR(35, 36) BR(38, 39)
            BR(40, 41) BR(43, 44) BR(46, 47) BR(49, 50) BR(52, 53)
            BR(41, 42) BR(44, 45) BR(47, 48) BR(50, 51) BR(53, 54)
#undef BR
#undef SUB3
#undef SUB5
#undef XV

            float T[16];
            #pragma unroll
            for (int q = 0; q < 16; ++q) T[q] = 0.0f;
            #pragma unroll
            for (int b = 0; b < NB; ++b) {
                float w = P[b];
                #pragma unroll
                for (int q = 0; q < 16; ++q) T[q] += w * tfs_s[b * 16 + q];
            }

            float X = xyz[(size_t)pg * 3 + 0];
            float Y = xyz[(size_t)pg * 3 + 1];
            float Z = xyz[(size_t)pg * 3 + 2];
            float xb0 = T[0] * X + T[1] * Y + T[2]  * Z + T[3];
            float xb1 = T[4] * X + T[5] * Y + T[6]  * Z + T[7];
            float xb2 = T[8] * X + T[9] * Y + T[10] * Z + T[11];

            float4 qv = *(const float4*)(quats + (size_t)pg * 4);
            {
                float inv = rsqrtf(qv.x * qv.x + qv.y * qv.y + qv.z * qv.z + qv.w * qv.w);
                qv.x *= inv; qv.y *= inv; qv.z *= inv; qv.w *= inv;
            }
            float r = qv.x, xq = qv.y, yq = qv.z, zq = qv.w;
            float R[3][3];
            R[0][0] = 1.0f - 2.0f * (yq * yq + zq * zq);
            R[0][1] = 2.0f * (xq * yq - r * zq);
            R[0][2] = 2.0f * (xq * zq + r * yq);
            R[1][0] = 2.0f * (xq * yq + r * zq);
            R[1][1] = 1.0f - 2.0f * (xq * xq + zq * zq);
            R[1][2] = 2.0f * (yq * zq - r * xq);
            R[2][0] = 2.0f * (xq * zq - r * yq);
            R[2][1] = 2.0f * (yq * zq + r * xq);
            R[2][2] = 1.0f - 2.0f * (xq * xq + yq * yq);

            float rb[3][3];
            #pragma unroll
            for (int i = 0; i < 3; ++i)
                #pragma unroll
                for (int k = 0; k < 3; ++k)
                    rb[i][k] = T[i * 4 + 0] * R[0][k] + T[i * 4 + 1] * R[1][k] + T[i * 4 + 2] * R[2][k];

            float m00 = rb[0][0], m01 = rb[0][1], m02 = rb[0][2];
            float m10 = rb[1][0], m11 = rb[1][1], m12 = rb[1][2];
            float m20 = rb[2][0], m21 = rb[2][1], m22 = rb[2][2];
            float t0 = 1.0f + m00 + m11 + m22;
            float t1 = 1.0f + m00 - m11 - m22;
            float t2 = 1.0f - m00 + m11 - m22;
            float t3 = 1.0f - m00 - m11 + m22;

            int best = 0; float tb = t0;
            if (t1 > tb) { best = 1; tb = t1; }
            if (t2 > tb) { best = 2; tb = t2; }
            if (t3 > tb) { best = 3; tb = t3; }

            float qa, qb2, qc, qd;
            if (best == 0)      { qa = t0;        qb2 = m21 - m12; qc = m02 - m20; qd = m10 - m01; }
            else if (best == 1) { qa = m21 - m12; qb2 = t1;        qc = m01 + m10; qd = m02 + m20; }
            else if (best == 2) { qa = m02 - m20; qb2 = m01 + m10; qc = t2;        qd = m12 + m21; }
            else                { qa = m10 - m01; qb2 = m02 + m20; qc = m12 + m21; qd = t3;        }
            float scale = 0.5f * rsqrtf(fmaxf(tb, 1e-8f));
            qa *= scale; qb2 *= scale; qc *= scale; qd *= scale;
            float qinv = rsqrtf(qa * qa + qb2 * qb2 + qc * qc + qd * qd);
            qa *= qinv; qb2 *= qinv; qc *= qinv; qd *= qinv;

            const size_t n = (size_t)Npts;
            out[(size_t)pg * 3 + 0] = xb0;
            out[(size_t)pg * 3 + 1] = xb1;
            out[(size_t)pg * 3 + 2] = xb2;
            float* ro = out + 3 * n + (size_t)pg * 9;
            #pragma unroll
            for (int i = 0; i < 3; ++i)
                #pragma unroll
                for (int k = 0; k < 3; ++k) ro[i * 3 + k] = rb[i][k];
            float* qo = out + 12 * n + (size_t)pg * 4;
            qo[0] = qa; qo[1] = qb2; qo[2] = qc; qo[3] = qd;
            float* to = out + 16 * n + (size_t)pg * 16;
            #pragma unroll
            for (int q = 0; q < 16; ++q) to[q] = T[q];
        }
        __syncwarp();
    }
}

extern "C" void kernel_launch(void* const* d_in, const int* in_sizes, int n_in,
                              void* d_out, int out_size)
{
    const float* xyz      = (const float*)d_in[0];
    const float* quats    = (const float*)d_in[1];
    const float* tfs      = (const float*)d_in[2];
    const float* aabb_min = (const float*)d_in[3];
    const float* aabb_max = (const float*)d_in[4];
    const float* W0 = (const float*)d_in[5];
    const float* b0 = (const float*)d_in[6];
    const float* W1 = (const float*)d_in[7];
    const float* b1 = (const float*)d_in[8];
    const float* W2 = (const float*)d_in[9];
    const float* b2 = (const float*)d_in[10];
    const float* W3 = (const float*)d_in[11];
    const float* b3 = (const float*)d_in[12];
    float* out = (float*)d_out;

    int Npts = in_sizes[0] / 3;
    int ntiles = (Npts + TILE - 1) / TILE;

    int sms = 0;
    cudaDeviceGetAttribute(&sms, cudaDevAttrMultiProcessorCount, 0);
    if (sms <= 0) sms = 148;
    int grid = (sms < ntiles) ? sms : ntiles;

    prep_kernel<<<64, 256>>>(W1, W2, W3);

    cudaFuncSetAttribute(skin_mma_kernel,
                         cudaFuncAttributeMaxDynamicSharedMemorySize, SMEM_TOTAL);
    skin_mma_kernel<<<grid, 384, SMEM_TOTAL>>>(
        xyz, quats, tfs, aabb_min, aabb_max,
        W0, b0, b1, b2, b3, out, Npts, ntiles);
}

// round 8
// speedup vs baseline: 7.9808x; 1.0893x over previous
#include <cuda_runtime.h>
#include <cuda_fp16.h>
#include <stdint.h>

// SkinningField R8: single-pass fp16 mma.sync, 512 threads (16 warps, 4/SMSP),
// TILE=512, incremental T-blend epilogue (low reg pressure), vectorized stores.

#define H    128
#define NB   55
#define TILE 512          // 16 warps x 32 points
#define NWARP 16
#define WSTR 136          // padded weight row stride (fp16 elems)
#define ESTR 61           // epilogue staging row stride (floats)

// smem byte offsets
#define OFF_W1  0
#define OFF_W2  34816
#define OFF_W3  69632
#define OFF_W0  87040                  // 384 floats
#define OFF_B0  (OFF_W0 + 1536)
#define OFF_B1  (OFF_B0 + 512)
#define OFF_B2  (OFF_B1 + 512)
#define OFF_B3  (OFF_B2 + 512)        // 64 floats
#define OFF_TFS (OFF_B3 + 256)        // 880 floats
#define OFF_ES  (OFF_TFS + 3520)      // 93888
#define SMEM_TOTAL (OFF_ES + NWARP * 32 * ESTR * 4)   // 218816

struct __align__(16) WBlob {
    __half w1[128 * WSTR];
    __half w2[128 * WSTR];
    __half w3[64 * WSTR];
};
__device__ WBlob g_wt;

// ---------------- helpers ----------------
__device__ __forceinline__ uint32_t smem_u32(const void* p) {
    uint32_t a;
    asm("{ .reg .u64 t; cvta.to.shared.u64 t, %1; cvt.u32.u64 %0, t; }" : "=r"(a) : "l"(p));
    return a;
}
__device__ __forceinline__ float sigf(float v) {
    return __fdividef(1.0f, 1.0f + __expf(-v));
}
__device__ __forceinline__ float sp(float v) {
    return fmaxf(v, 0.0f) + __logf(1.0f + __expf(-fabsf(v)));
}
__device__ __forceinline__ void sm3(float a, float b, float c, float& oa, float& ob, float& oc) {
    float m = fmaxf(a, fmaxf(b, c));
    float ea = __expf(a - m), eb = __expf(b - m), ec = __expf(c - m);
    float inv = __fdividef(1.0f, ea + eb + ec);
    oa = ea * inv; ob = eb * inv; oc = ec * inv;
}
__device__ __forceinline__ void sm5(float a, float b, float c, float d, float e,
                                    float& oa, float& ob, float& oc, float& od, float& oe) {
    float m = fmaxf(fmaxf(a, b), fmaxf(fmaxf(c, d), e));
    float ea = __expf(a - m), eb = __expf(b - m), ec = __expf(c - m),
          ed = __expf(d - m), ee = __expf(e - m);
    float inv = __fdividef(1.0f, ea + eb + ec + ed + ee);
    oa = ea * inv; ob = eb * inv; oc = ec * inv; od = ed * inv; oe = ee * inv;
}
__device__ __forceinline__ uint32_t pack_h2(float h0, float h1) {
    uint32_t w;
    asm("cvt.rn.f16x2.f32 %0, %1, %2;" : "=r"(w) : "f"(h1), "f"(h0));
    return w;
}

__device__ __forceinline__ void mma_f16(float& d0, float& d1, float& d2, float& d3,
                                        uint32_t a0, uint32_t a1, uint32_t a2, uint32_t a3,
                                        uint32_t b0, uint32_t b1) {
    asm volatile("mma.sync.aligned.m16n8k16.row.col.f32.f16.f16.f32 "
                 "{%0,%1,%2,%3}, {%4,%5,%6,%7}, {%8,%9}, {%0,%1,%2,%3};"
                 : "+f"(d0), "+f"(d1), "+f"(d2), "+f"(d3)
                 : "r"(a0), "r"(a1), "r"(a2), "r"(a3), "r"(b0), "r"(b1));
}

__device__ __forceinline__ void ldx4(uint32_t b[4], uint32_t base, int lane, int n0, int k0) {
    int grp = lane >> 3, r = lane & 7;
    int row = n0 + r + ((grp >> 1) << 3);
    int col = k0 + ((grp & 1) << 3);
    uint32_t addr = base + (uint32_t)(row * WSTR + col) * 2u;
    asm volatile("ldmatrix.sync.aligned.m8n8.x4.shared.b16 {%0,%1,%2,%3}, [%4];"
                 : "=r"(b[0]), "=r"(b[1]), "=r"(b[2]), "=r"(b[3]) : "r"(addr));
}

template <int NC>
__device__ __forceinline__ void gemm_layer(float acc[][4], const uint32_t ahi[8][4],
                                           uint32_t wsm, int lane) {
    #pragma unroll
    for (int j = 0; j < NC; ++j) { acc[j][0] = 0.f; acc[j][1] = 0.f; acc[j][2] = 0.f; acc[j][3] = 0.f; }
    #pragma unroll
    for (int kk = 0; kk < 8; ++kk) {
        #pragma unroll
        for (int jj = 0; jj < NC / 2; ++jj) {
            uint32_t bh[4];
            ldx4(bh, wsm, lane, 16 * jj, 16 * kk);
            float* aL = acc[2 * jj];
            float* aR = acc[2 * jj + 1];
            mma_f16(aL[0], aL[1], aL[2], aL[3], ahi[kk][0], ahi[kk][1], ahi[kk][2], ahi[kk][3], bh[0], bh[1]);
            mma_f16(aR[0], aR[1], aR[2], aR[3], ahi[kk][0], ahi[kk][1], ahi[kk][2], ahi[kk][3], bh[2], bh[3]);
        }
    }
}

__device__ __forceinline__ void act_pack(const float acc[][4], const float* bias_s,
                                         uint32_t ahi[8][4], int lane) {
    const int cbase = 2 * (lane & 3);
    #pragma unroll
    for (int j = 0; j < 16; ++j) {
        int c = 8 * j + cbase;
        float h0 = sp(acc[j][0] + bias_s[c]);
        float h1 = sp(acc[j][1] + bias_s[c + 1]);
        float h2 = sp(acc[j][2] + bias_s[c]);
        float h3 = sp(acc[j][3] + bias_s[c + 1]);
        int kk = j >> 1, half = (j & 1) << 1;
        ahi[kk][half]     = pack_h2(h0, h1);
        ahi[kk][half + 1] = pack_h2(h2, h3);
    }
}

// accumulate one bone's transform into T
__device__ __forceinline__ void tacc(float T[16], const float* tfs_s, int b, float w) {
    #pragma unroll
    for (int q = 0; q < 16; ++q) T[q] += w * tfs_s[b * 16 + q];
}

// ---------------- prep: transpose weights into g_wt ----------------
__global__ void prep_kernel(const float* __restrict__ W1, const float* __restrict__ W2,
                            const float* __restrict__ W3) {
    int tid = blockIdx.x * blockDim.x + threadIdx.x;
    int stride = gridDim.x * blockDim.x;
    for (int o = tid; o < 128 * WSTR; o += stride) {
        int n = o / WSTR, k = o % WSTR;
        float f1 = 0.f, f2 = 0.f;
        if (k < 128) { f1 = W1[k * 128 + n]; f2 = W2[k * 128 + n]; }
        g_wt.w1[o] = __float2half_rn(f1);
        g_wt.w2[o] = __float2half_rn(f2);
    }
    for (int o = tid; o < 64 * WSTR; o += stride) {
        int n = o / WSTR, k = o % WSTR;
        float f = (n < 59 && k < 128) ? W3[k * 59 + n] : 0.f;
        g_wt.w3[o] = __float2half_rn(f);
    }
}

// ---------------- main kernel ----------------
__global__ void __launch_bounds__(512, 1)
skin_mma_kernel(const float* __restrict__ xyz,  const float* __restrict__ quats,
                const float* __restrict__ tfs,  const float* __restrict__ aabb_min,
                const float* __restrict__ aabb_max,
                const float* __restrict__ W0, const float* __restrict__ b0,
                const float* __restrict__ b1, const float* __restrict__ b2,
                const float* __restrict__ b3,
                float* __restrict__ out, int Npts, int ntiles)
{
    extern __shared__ char smem[];
    const int tid  = threadIdx.x;
    const int wid  = tid >> 5;
    const int lane = tid & 31;

    // stage weight blob
    {
        const uint4* src = (const uint4*)&g_wt;
        uint4* dst = (uint4*)smem;
        for (int i = tid; i < (int)(sizeof(WBlob) / 16); i += 512) dst[i] = src[i];
    }
    float* w0s  = (float*)(smem + OFF_W0);
    float* b0s  = (float*)(smem + OFF_B0);
    float* b1s  = (float*)(smem + OFF_B1);
    float* b2s  = (float*)(smem + OFF_B2);
    float* b3s  = (float*)(smem + OFF_B3);
    float* tfs_s = (float*)(smem + OFF_TFS);
    for (int i = tid; i < 3 * H; i += 512) w0s[i] = W0[i];
    if (tid < H) { b0s[tid] = b0[tid]; b1s[tid] = b1[tid]; b2s[tid] = b2[tid]; }
    if (tid < 64) b3s[tid] = (tid < 59) ? b3[tid] : 0.0f;
    for (int i = tid; i < NB * 16; i += 512) tfs_s[i] = tfs[i];
    __syncthreads();

    const uint32_t u_w1 = smem_u32(smem + OFF_W1);
    const uint32_t u_w2 = smem_u32(smem + OFF_W2);
    const uint32_t u_w3 = smem_u32(smem + OFF_W3);
    float* es_w = (float*)(smem + OFF_ES) + wid * (32 * ESTR);

    const float amn0 = __ldg(aabb_min + 0), amn1 = __ldg(aabb_min + 1), amn2 = __ldg(aabb_min + 2);
    const float amx0 = __ldg(aabb_max + 0), amx1 = __ldg(aabb_max + 1), amx2 = __ldg(aabb_max + 2);
    const float sc0 = 2.0f / (amx0 - amn0), sc1 = 2.0f / (amx1 - amn1), sc2 = 2.0f / (amx2 - amn2);

    const int g = lane >> 2;          // row group 0..7
    const int cbase = 2 * (lane & 3);

    for (int t = blockIdx.x; t < ntiles; t += gridDim.x) {
        const int pbase_w = t * TILE + wid * 32;

        // ---- two 16-point MLP passes per warp ----
        #pragma unroll
        for (int hf = 0; hf < 2; ++hf) {
            const int base16 = pbase_w + hf * 16;
            uint32_t ahi[8][4];
            float acc[16][4];

            // layer 0: 3 -> 128 fp32, pack to fp16 A frags
            {
                int pA = base16 + g;     if (pA >= Npts) pA = Npts - 1;
                int pB = base16 + g + 8; if (pB >= Npts) pB = Npts - 1;
                float xA0 = (xyz[(size_t)pA * 3 + 0] - amn0) * sc0 - 1.0f;
                float xA1 = (xyz[(size_t)pA * 3 + 1] - amn1) * sc1 - 1.0f;
                float xA2 = (xyz[(size_t)pA * 3 + 2] - amn2) * sc2 - 1.0f;
                float xB0 = (xyz[(size_t)pB * 3 + 0] - amn0) * sc0 - 1.0f;
                float xB1 = (xyz[(size_t)pB * 3 + 1] - amn1) * sc1 - 1.0f;
                float xB2 = (xyz[(size_t)pB * 3 + 2] - amn2) * sc2 - 1.0f;
                #pragma unroll
                for (int j = 0; j < 16; ++j) {
                    int c = 8 * j + cbase;
                    float w0c = w0s[c],     w1c = w0s[128 + c],     w2c = w0s[256 + c];
                    float w0d = w0s[c + 1], w1d = w0s[128 + c + 1], w2d = w0s[256 + c + 1];
                    float h0 = sp(b0s[c]     + xA0 * w0c + xA1 * w1c + xA2 * w2c);
                    float h1 = sp(b0s[c + 1] + xA0 * w0d + xA1 * w1d + xA2 * w2d);
                    float h2 = sp(b0s[c]     + xB0 * w0c + xB1 * w1c + xB2 * w2c);
                    float h3 = sp(b0s[c + 1] + xB0 * w0d + xB1 * w1d + xB2 * w2d);
                    int kk = j >> 1, half = (j & 1) << 1;
                    ahi[kk][half]     = pack_h2(h0, h1);
                    ahi[kk][half + 1] = pack_h2(h2, h3);
                }
            }

            gemm_layer<16>(acc, ahi, u_w1, lane);
            act_pack(acc, b1s, ahi, lane);
            gemm_layer<16>(acc, ahi, u_w2, lane);
            act_pack(acc, b2s, ahi, lane);
            gemm_layer<8>(acc, ahi, u_w3, lane);

            // stage logits (rows hf*16 + g / +8; guard col < 59)
            __syncwarp();
            #pragma unroll
            for (int j = 0; j < 8; ++j) {
                int c = 8 * j + cbase;
                int r0 = hf * 16 + g, r1 = r0 + 8;
                if (c < 59) {
                    es_w[r0 * ESTR + c] = acc[j][0] + b3s[c];
                    es_w[r1 * ESTR + c] = acc[j][2] + b3s[c];
                }
                if (c + 1 < 59) {
                    es_w[r0 * ESTR + c + 1] = acc[j][1] + b3s[c + 1];
                    es_w[r1 * ESTR + c + 1] = acc[j][3] + b3s[c + 1];
                }
            }
            __syncwarp();
        }

        // ---- epilogue: ALL 32 lanes, one point each; incremental T blend ----
        const int pg = pbase_w + lane;
        if (pg < Npts) {
            const float* xr = es_w + lane * ESTR;
#define XV(i) xr[i]
            float T[16];
            #pragma unroll
            for (int q = 0; q < 16; ++q) T[q] = 0.0f;

            float o1, o2, o3, o4, o5;
            // root
            float s0 = sigf(XV(0));
            sm3(XV(1), XV(2), XV(3), o1, o2, o3);
            float P1 = s0 * o1, P2 = s0 * o2, P3 = s0 * o3;
            tacc(T, tfs_s, 0, 1.0f - s0);

            // BR(par,ch): child pending, parent final
#define BRP(Pp, pidx, cidx, Pc) { float s_ = sigf(XV(cidx)); Pc = Pp * s_; \
                                  tacc(T, tfs_s, pidx, Pp * (1.0f - s_)); }
            // BR with leaf child: both final
#define BRL(Pp, pidx, cidx)     { float s_ = sigf(XV(cidx)); \
                                  tacc(T, tfs_s, cidx, Pp * s_); \
                                  tacc(T, tfs_s, pidx, Pp * (1.0f - s_)); }

            float P4, P5, P6;
            BRP(P1, 1, 4, P4)  BRP(P2, 2, 5, P5)  BRP(P3, 3, 6, P6)
            float P7, P8, P9;
            BRP(P4, 4, 7, P7)  BRP(P5, 5, 8, P8)  BRP(P6, 6, 9, P9)
            BRL(P7, 7, 10)     BRL(P8, 8, 11)

            // SUB3(9,55,[12,13,14]) -> children pending
            float P12, P13, P14;
            {
                float gg = sigf(XV(55));
                sm3(XV(12), XV(13), XV(14), o1, o2, o3);
                float a = P9 * gg;
                P12 = a * o1; P13 = a * o2; P14 = a * o3;
                tacc(T, tfs_s, 9, P9 * (1.0f - gg));
            }
            float P15, P16, P17;
            BRP(P12, 12, 15, P15) BRP(P13, 13, 16, P16) BRP(P14, 14, 17, P17)
            float P18, P19;
            BRP(P16, 16, 18, P18) BRP(P17, 17, 19, P19)
            float P20, P21;
            BRP(P18, 18, 20, P20) BRP(P19, 19, 21, P21)

            // SUB3(15,56,[22,23,24]) -> all leaves
            {
                float gg = sigf(XV(56));
                sm3(XV(22), XV(23), XV(24), o1, o2, o3);
                float a = P15 * gg;
                tacc(T, tfs_s, 22, a * o1);
                tacc(T, tfs_s, 23, a * o2);
                tacc(T, tfs_s, 24, a * o3);
                tacc(T, tfs_s, 15, P15 * (1.0f - gg));
            }
            // SUB5(20,57,[25,28,31,34,37]) -> children pending
            float P25, P28, P31, P34, P37;
            {
                float gg = sigf(XV(57));
                sm5(XV(25), XV(28), XV(31), XV(34), XV(37), o1, o2, o3, o4, o5);
                float a = P20 * gg;
                P25 = a * o1; P28 = a * o2; P31 = a * o3; P34 = a * o4; P37 = a * o5;
                tacc(T, tfs_s, 20, P20 * (1.0f - gg));
            }
            // chains 25->26->27 etc.
            {
                float Pc;
                BRP(P25, 25, 26, Pc) BRL(Pc, 26, 27)
                BRP(P28, 28, 29, Pc) BRL(Pc, 29, 30)
                BRP(P31, 31, 32, Pc) BRL(Pc, 32, 33)
                BRP(P34, 34, 35, Pc) BRL(Pc, 35, 36)
                BRP(P37, 37, 38, Pc) BRL(Pc, 38, 39)
            }
            // SUB5(21,58,[40,43,46,49,52])
            float P40, P43, P46, P49, P52;
            {
                float gg = sigf(XV(58));
                sm5(XV(40), XV(43), XV(46), XV(49), XV(52), o1, o2, o3, o4, o5);
                float a = P21 * gg;
                P40 = a * o1; P43 = a * o2; P46 = a * o3; P49 = a * o4; P52 = a * o5;
                tacc(T, tfs_s, 21, P21 * (1.0f - gg));
            }
            {
                float Pc;
                BRP(P40, 40, 41, Pc) BRL(Pc, 41, 42)
                BRP(P43, 43, 44, Pc) BRL(Pc, 44, 45)
                BRP(P46, 46, 47, Pc) BRL(Pc, 47, 48)
                BRP(P49, 49, 50, Pc) BRL(Pc, 50, 51)
                BRP(P52, 52, 53, Pc) BRL(Pc, 53, 54)
            }
#undef BRP
#undef BRL
#undef XV

            float X = xyz[(size_t)pg * 3 + 0];
            float Y = xyz[(size_t)pg * 3 + 1];
            float Z = xyz[(size_t)pg * 3 + 2];
            float xb0 = T[0] * X + T[1] * Y + T[2]  * Z + T[3];
            float xb1 = T[4] * X + T[5] * Y + T[6]  * Z + T[7];
            float xb2 = T[8] * X + T[9] * Y + T[10] * Z + T[11];

            float4 qv = *(const float4*)(quats + (size_t)pg * 4);
            {
                float inv = rsqrtf(qv.x * qv.x + qv.y * qv.y + qv.z * qv.z + qv.w * qv.w);
                qv.x *= inv; qv.y *= inv; qv.z *= inv; qv.w *= inv;
            }
            float r = qv.x, xq = qv.y, yq = qv.z, zq = qv.w;
            float R[3][3];
            R[0][0] = 1.0f - 2.0f * (yq * yq + zq * zq);
            R[0][1] = 2.0f * (xq * yq - r * zq);
            R[0][2] = 2.0f * (xq * zq + r * yq);
            R[1][0] = 2.0f * (xq * yq + r * zq);
            R[1][1] = 1.0f - 2.0f * (xq * xq + zq * zq);
            R[1][2] = 2.0f * (yq * zq - r * xq);
            R[2][0] = 2.0f * (xq * zq - r * yq);
            R[2][1] = 2.0f * (yq * zq + r * xq);
            R[2][2] = 1.0f - 2.0f * (xq * xq + yq * yq);

            float rb[3][3];
            #pragma unroll
            for (int i = 0; i < 3; ++i)
                #pragma unroll
                for (int k = 0; k < 3; ++k)
                    rb[i][k] = T[i * 4 + 0] * R[0][k] + T[i * 4 + 1] * R[1][k] + T[i * 4 + 2] * R[2][k];

            float m00 = rb[0][0], m01 = rb[0][1], m02 = rb[0][2];
            float m10 = rb[1][0], m11 = rb[1][1], m12 = rb[1][2];
            float m20 = rb[2][0], m21 = rb[2][1], m22 = rb[2][2];
            float t0 = 1.0f + m00 + m11 + m22;
            float t1 = 1.0f + m00 - m11 - m22;
            float t2 = 1.0f - m00 + m11 - m22;
            float t3 = 1.0f - m00 - m11 + m22;

            int best = 0; float tb = t0;
            if (t1 > tb) { best = 1; tb = t1; }
            if (t2 > tb) { best = 2; tb = t2; }
            if (t3 > tb) { best = 3; tb = t3; }

            float qa, qb2, qc, qd;
            if (best == 0)      { qa = t0;        qb2 = m21 - m12; qc = m02 - m20; qd = m10 - m01; }
            else if (best == 1) { qa = m21 - m12; qb2 = t1;        qc = m01 + m10; qd = m02 + m20; }
            else if (best == 2) { qa = m02 - m20; qb2 = m01 + m10; qc = t2;        qd = m12 + m21; }
            else                { qa = m10 - m01; qb2 = m02 + m20; qc = m12 + m21; qd = t3;        }
            float scale = 0.5f * rsqrtf(fmaxf(tb, 1e-8f));
            qa *= scale; qb2 *= scale; qc *= scale; qd *= scale;
            float qinv = rsqrtf(qa * qa + qb2 * qb2 + qc * qc + qd * qd);
            qa *= qinv; qb2 *= qinv; qc *= qinv; qd *= qinv;

            const size_t n = (size_t)Npts;
            out[(size_t)pg * 3 + 0] = xb0;
            out[(size_t)pg * 3 + 1] = xb1;
            out[(size_t)pg * 3 + 2] = xb2;
            float* ro = out + 3 * n + (size_t)pg * 9;
            #pragma unroll
            for (int i = 0; i < 3; ++i)
                #pragma unroll
                for (int k = 0; k < 3; ++k) ro[i * 3 + k] = rb[i][k];
            float4* qo = (float4*)(out + 12 * n + (size_t)pg * 4);
            *qo = make_float4(qa, qb2, qc, qd);
            float4* to = (float4*)(out + 16 * n + (size_t)pg * 16);
            to[0] = make_float4(T[0],  T[1],  T[2],  T[3]);
            to[1] = make_float4(T[4],  T[5],  T[6],  T[7]);
            to[2] = make_float4(T[8],  T[9],  T[10], T[11]);
            to[3] = make_float4(T[12], T[13], T[14], T[15]);
        }
        __syncwarp();
    }
}

extern "C" void kernel_launch(void* const* d_in, const int* in_sizes, int n_in,
                              void* d_out, int out_size)
{
    const float* xyz      = (const float*)d_in[0];
    const float* quats    = (const float*)d_in[1];
    const float* tfs      = (const float*)d_in[2];
    const float* aabb_min = (const float*)d_in[3];
    const float* aabb_max = (const float*)d_in[4];
    const float* W0 = (const float*)d_in[5];
    const float* b0 = (const float*)d_in[6];
    const float* W1 = (const float*)d_in[7];
    const float* b1 = (const float*)d_in[8];
    const float* W2 = (const float*)d_in[9];
    const float* b2 = (const float*)d_in[10];
    const float* W3 = (const float*)d_in[11];
    const float* b3 = (const float*)d_in[12];
    float* out = (float*)d_out;

    int Npts = in_sizes[0] / 3;
    int ntiles = (Npts + TILE - 1) / TILE;

    int sms = 0;
    cudaDeviceGetAttribute(&sms, cudaDevAttrMultiProcessorCount, 0);
    if (sms <= 0) sms = 148;
    int grid = (sms < ntiles) ? sms : ntiles;

    prep_kernel<<<64, 256>>>(W1, W2, W3);

    cudaFuncSetAttribute(skin_mma_kernel,
                         cudaFuncAttributeMaxDynamicSharedMemorySize, SMEM_TOTAL);
    skin_mma_kernel<<<grid, 512, SMEM_TOTAL>>>(
        xyz, quats, tfs, aabb_min, aabb_max,
        W0, b0, b1, b2, b3, out, Npts, ntiles);
}

// round 9
// speedup vs baseline: 8.1200x; 1.0174x over previous
#include <cuda_runtime.h>
#include <cuda_fp16.h>
#include <stdint.h>

// SkinningField R9: R8 + warp phase-staggering (odd warps run halves in
// reverse order to overlap tensor/MUFU bursts) + softplus exp via
// ex2.approx.f16x2 (1 MUFU per exp-pair).

#define H    128
#define NB   55
#define TILE 512          // 16 warps x 32 points
#define NWARP 16
#define WSTR 136
#define ESTR 61

#define OFF_W1  0
#define OFF_W2  34816
#define OFF_W3  69632
#define OFF_W0  87040
#define OFF_B0  (OFF_W0 + 1536)
#define OFF_B1  (OFF_B0 + 512)
#define OFF_B2  (OFF_B1 + 512)
#define OFF_B3  (OFF_B2 + 512)
#define OFF_TFS (OFF_B3 + 256)
#define OFF_ES  (OFF_TFS + 3520)
#define SMEM_TOTAL (OFF_ES + NWARP * 32 * ESTR * 4)   // 218816

struct __align__(16) WBlob {
    __half w1[128 * WSTR];
    __half w2[128 * WSTR];
    __half w3[64 * WSTR];
};
__device__ WBlob g_wt;

// ---------------- helpers ----------------
__device__ __forceinline__ uint32_t smem_u32(const void* p) {
    uint32_t a;
    asm("{ .reg .u64 t; cvta.to.shared.u64 t, %1; cvt.u32.u64 %0, t; }" : "=r"(a) : "l"(p));
    return a;
}
__device__ __forceinline__ float sigf(float v) {
    return __fdividef(1.0f, 1.0f + __expf(-v));
}
__device__ __forceinline__ void sm3(float a, float b, float c, float& oa, float& ob, float& oc) {
    float m = fmaxf(a, fmaxf(b, c));
    float ea = __expf(a - m), eb = __expf(b - m), ec = __expf(c - m);
    float inv = __fdividef(1.0f, ea + eb + ec);
    oa = ea * inv; ob = eb * inv; oc = ec * inv;
}
__device__ __forceinline__ void sm5(float a, float b, float c, float d, float e,
                                    float& oa, float& ob, float& oc, float& od, float& oe) {
    float m = fmaxf(fmaxf(a, b), fmaxf(fmaxf(c, d), e));
    float ea = __expf(a - m), eb = __expf(b - m), ec = __expf(c - m),
          ed = __expf(d - m), ee = __expf(e - m);
    float inv = __fdividef(1.0f, ea + eb + ec + ed + ee);
    oa = ea * inv; ob = eb * inv; oc = ec * inv; od = ed * inv; oe = ee * inv;
}
__device__ __forceinline__ uint32_t pack_h2(float h0, float h1) {
    uint32_t w;
    asm("cvt.rn.f16x2.f32 %0, %1, %2;" : "=r"(w) : "f"(h1), "f"(h0));
    return w;
}
// e^t for a packed f16x2 pair (t in f16x2), via single MUFU ex2.approx.f16x2
__device__ __forceinline__ uint32_t h2exp_fast(uint32_t t) {
    uint32_t r;
    const uint32_t log2e_h2 = 0x3dc53dc5u;  // (1.4427, 1.4427) fp16x2
    asm("{ .reg .b32 s;\n\t"
        "mul.rn.f16x2 s, %1, %2;\n\t"
        "ex2.approx.f16x2 %0, s; }"
        : "=r"(r) : "r"(t), "r"(log2e_h2));
    return r;
}
// softplus on a pair of floats using one fp16x2 exp + two f32 LG2
__device__ __forceinline__ void sp2(float y0, float y1, float& o0, float& o1) {
    uint32_t t = pack_h2(-fabsf(y0), -fabsf(y1));
    uint32_t e = h2exp_fast(t);
    __half2 eh = *reinterpret_cast<__half2*>(&e);
    float e0 = __low2float(eh), e1 = __high2float(eh);
    o0 = fmaxf(y0, 0.0f) + __logf(1.0f + e0);
    o1 = fmaxf(y1, 0.0f) + __logf(1.0f + e1);
}

__device__ __forceinline__ void mma_f16(float& d0, float& d1, float& d2, float& d3,
                                        uint32_t a0, uint32_t a1, uint32_t a2, uint32_t a3,
                                        uint32_t b0, uint32_t b1) {
    asm volatile("mma.sync.aligned.m16n8k16.row.col.f32.f16.f16.f32 "
                 "{%0,%1,%2,%3}, {%4,%5,%6,%7}, {%8,%9}, {%0,%1,%2,%3};"
                 : "+f"(d0), "+f"(d1), "+f"(d2), "+f"(d3)
                 : "r"(a0), "r"(a1), "r"(a2), "r"(a3), "r"(b0), "r"(b1));
}

__device__ __forceinline__ void ldx4(uint32_t b[4], uint32_t base, int lane, int n0, int k0) {
    int grp = lane >> 3, r = lane & 7;
    int row = n0 + r + ((grp >> 1) << 3);
    int col = k0 + ((grp & 1) << 3);
    uint32_t addr = base + (uint32_t)(row * WSTR + col) * 2u;
    asm volatile("ldmatrix.sync.aligned.m8n8.x4.shared.b16 {%0,%1,%2,%3}, [%4];"
                 : "=r"(b[0]), "=r"(b[1]), "=r"(b[2]), "=r"(b[3]) : "r"(addr));
}

template <int NC>
__device__ __forceinline__ void gemm_layer(float acc[][4], const uint32_t ahi[8][4],
                                           uint32_t wsm, int lane) {
    #pragma unroll
    for (int j = 0; j < NC; ++j) { acc[j][0] = 0.f; acc[j][1] = 0.f; acc[j][2] = 0.f; acc[j][3] = 0.f; }
    #pragma unroll
    for (int kk = 0; kk < 8; ++kk) {
        #pragma unroll
        for (int jj = 0; jj < NC / 2; ++jj) {
            uint32_t bh[4];
            ldx4(bh, wsm, lane, 16 * jj, 16 * kk);
            float* aL = acc[2 * jj];
            float* aR = acc[2 * jj + 1];
            mma_f16(aL[0], aL[1], aL[2], aL[3], ahi[kk][0], ahi[kk][1], ahi[kk][2], ahi[kk][3], bh[0], bh[1]);
            mma_f16(aR[0], aR[1], aR[2], aR[3], ahi[kk][0], ahi[kk][1], ahi[kk][2], ahi[kk][3], bh[2], bh[3]);
        }
    }
}

__device__ __forceinline__ void act_pack(const float acc[][4], const float* bias_s,
                                         uint32_t ahi[8][4], int lane) {
    const int cbase = 2 * (lane & 3);
    #pragma unroll
    for (int j = 0; j < 16; ++j) {
        int c = 8 * j + cbase;
        float h0, h1, h2, h3;
        sp2(acc[j][0] + bias_s[c], acc[j][1] + bias_s[c + 1], h0, h1);
        sp2(acc[j][2] + bias_s[c], acc[j][3] + bias_s[c + 1], h2, h3);
        int kk = j >> 1, half = (j & 1) << 1;
        ahi[kk][half]     = pack_h2(h0, h1);
        ahi[kk][half + 1] = pack_h2(h2, h3);
    }
}

__device__ __forceinline__ void tacc(float T[16], const float* tfs_s, int b, float w) {
    #pragma unroll
    for (int q = 0; q < 16; ++q) T[q] += w * tfs_s[b * 16 + q];
}

// ---------------- prep ----------------
__global__ void prep_kernel(const float* __restrict__ W1, const float* __restrict__ W2,
                            const float* __restrict__ W3) {
    int tid = blockIdx.x * blockDim.x + threadIdx.x;
    int stride = gridDim.x * blockDim.x;
    for (int o = tid; o < 128 * WSTR; o += stride) {
        int n = o / WSTR, k = o % WSTR;
        float f1 = 0.f, f2 = 0.f;
        if (k < 128) { f1 = W1[k * 128 + n]; f2 = W2[k * 128 + n]; }
        g_wt.w1[o] = __float2half_rn(f1);
        g_wt.w2[o] = __float2half_rn(f2);
    }
    for (int o = tid; o < 64 * WSTR; o += stride) {
        int n = o / WSTR, k = o % WSTR;
        float f = (n < 59 && k < 128) ? W3[k * 59 + n] : 0.f;
        g_wt.w3[o] = __float2half_rn(f);
    }
}

// ---------------- main kernel ----------------
__global__ void __launch_bounds__(512, 1)
skin_mma_kernel(const float* __restrict__ xyz,  const float* __restrict__ quats,
                const float* __restrict__ tfs,  const float* __restrict__ aabb_min,
                const float* __restrict__ aabb_max,
                const float* __restrict__ W0, const float* __restrict__ b0,
                const float* __restrict__ b1, const float* __restrict__ b2,
                const float* __restrict__ b3,
                float* __restrict__ out, int Npts, int ntiles)
{
    extern __shared__ char smem[];
    const int tid  = threadIdx.x;
    const int wid  = tid >> 5;
    const int lane = tid & 31;

    {
        const uint4* src = (const uint4*)&g_wt;
        uint4* dst = (uint4*)smem;
        for (int i = tid; i < (int)(sizeof(WBlob) / 16); i += 512) dst[i] = src[i];
    }
    float* w0s  = (float*)(smem + OFF_W0);
    float* b0s  = (float*)(smem + OFF_B0);
    float* b1s  = (float*)(smem + OFF_B1);
    float* b2s  = (float*)(smem + OFF_B2);
    float* b3s  = (float*)(smem + OFF_B3);
    float* tfs_s = (float*)(smem + OFF_TFS);
    for (int i = tid; i < 3 * H; i += 512) w0s[i] = W0[i];
    if (tid < H) { b0s[tid] = b0[tid]; b1s[tid] = b1[tid]; b2s[tid] = b2[tid]; }
    if (tid < 64) b3s[tid] = (tid < 59) ? b3[tid] : 0.0f;
    for (int i = tid; i < NB * 16; i += 512) tfs_s[i] = tfs[i];
    __syncthreads();

    const uint32_t u_w1 = smem_u32(smem + OFF_W1);
    const uint32_t u_w2 = smem_u32(smem + OFF_W2);
    const uint32_t u_w3 = smem_u32(smem + OFF_W3);
    float* es_w = (float*)(smem + OFF_ES) + wid * (32 * ESTR);

    const float amn0 = __ldg(aabb_min + 0), amn1 = __ldg(aabb_min + 1), amn2 = __ldg(aabb_min + 2);
    const float amx0 = __ldg(aabb_max + 0), amx1 = __ldg(aabb_max + 1), amx2 = __ldg(aabb_max + 2);
    const float sc0 = 2.0f / (amx0 - amn0), sc1 = 2.0f / (amx1 - amn1), sc2 = 2.0f / (amx2 - amn2);

    const int g = lane >> 2;
    const int cbase = 2 * (lane & 3);
    const int wpar = wid & 1;         // phase stagger: odd warps reverse half order

    for (int t = blockIdx.x; t < ntiles; t += gridDim.x) {
        const int pbase_w = t * TILE + wid * 32;

        #pragma unroll
        for (int hh = 0; hh < 2; ++hh) {
            const int hf = hh ^ wpar;
            const int base16 = pbase_w + hf * 16;
            uint32_t ahi[8][4];
            float acc[16][4];

            // layer 0: 3 -> 128 fp32, pack to fp16 A frags
            {
                int pA = base16 + g;     if (pA >= Npts) pA = Npts - 1;
                int pB = base16 + g + 8; if (pB >= Npts) pB = Npts - 1;
                float xA0 = (xyz[(size_t)pA * 3 + 0] - amn0) * sc0 - 1.0f;
                float xA1 = (xyz[(size_t)pA * 3 + 1] - amn1) * sc1 - 1.0f;
                float xA2 = (xyz[(size_t)pA * 3 + 2] - amn2) * sc2 - 1.0f;
                float xB0 = (xyz[(size_t)pB * 3 + 0] - amn0) * sc0 - 1.0f;
                float xB1 = (xyz[(size_t)pB * 3 + 1] - amn1) * sc1 - 1.0f;
                float xB2 = (xyz[(size_t)pB * 3 + 2] - amn2) * sc2 - 1.0f;
                #pragma unroll
                for (int j = 0; j < 16; ++j) {
                    int c = 8 * j + cbase;
                    float w0c = w0s[c],     w1c = w0s[128 + c],     w2c = w0s[256 + c];
                    float w0d = w0s[c + 1], w1d = w0s[128 + c + 1], w2d = w0s[256 + c + 1];
                    float y0 = b0s[c]     + xA0 * w0c + xA1 * w1c + xA2 * w2c;
                    float y1 = b0s[c + 1] + xA0 * w0d + xA1 * w1d + xA2 * w2d;
                    float y2 = b0s[c]     + xB0 * w0c + xB1 * w1c + xB2 * w2c;
                    float y3 = b0s[c + 1] + xB0 * w0d + xB1 * w1d + xB2 * w2d;
                    float h0, h1, h2, h3;
                    sp2(y0, y1, h0, h1);
                    sp2(y2, y3, h2, h3);
                    int kk = j >> 1, half = (j & 1) << 1;
                    ahi[kk][half]     = pack_h2(h0, h1);
                    ahi[kk][half + 1] = pack_h2(h2, h3);
                }
            }

            gemm_layer<16>(acc, ahi, u_w1, lane);
            act_pack(acc, b1s, ahi, lane);
            gemm_layer<16>(acc, ahi, u_w2, lane);
            act_pack(acc, b2s, ahi, lane);
            gemm_layer<8>(acc, ahi, u_w3, lane);

            __syncwarp();
            #pragma unroll
            for (int j = 0; j < 8; ++j) {
                int c = 8 * j + cbase;
                int r0 = hf * 16 + g, r1 = r0 + 8;
                if (c < 59) {
                    es_w[r0 * ESTR + c] = acc[j][0] + b3s[c];
                    es_w[r1 * ESTR + c] = acc[j][2] + b3s[c];
                }
                if (c + 1 < 59) {
                    es_w[r0 * ESTR + c + 1] = acc[j][1] + b3s[c + 1];
                    es_w[r1 * ESTR + c + 1] = acc[j][3] + b3s[c + 1];
                }
            }
            __syncwarp();
        }

        // ---- epilogue: ALL 32 lanes, one point each; incremental T blend ----
        const int pg = pbase_w + lane;
        if (pg < Npts) {
            const float* xr = es_w + lane * ESTR;
#define XV(i) xr[i]
            float T[16];
            #pragma unroll
            for (int q = 0; q < 16; ++q) T[q] = 0.0f;

            float o1, o2, o3, o4, o5;
            float s0 = sigf(XV(0));
            sm3(XV(1), XV(2), XV(3), o1, o2, o3);
            float P1 = s0 * o1, P2 = s0 * o2, P3 = s0 * o3;
            tacc(T, tfs_s, 0, 1.0f - s0);

#define BRP(Pp, pidx, cidx, Pc) { float s_ = sigf(XV(cidx)); Pc = Pp * s_; \
                                  tacc(T, tfs_s, pidx, Pp * (1.0f - s_)); }
#define BRL(Pp, pidx, cidx)     { float s_ = sigf(XV(cidx)); \
                                  tacc(T, tfs_s, cidx, Pp * s_); \
                                  tacc(T, tfs_s, pidx, Pp * (1.0f - s_)); }

            float P4, P5, P6;
            BRP(P1, 1, 4, P4)  BRP(P2, 2, 5, P5)  BRP(P3, 3, 6, P6)
            float P7, P8, P9;
            BRP(P4, 4, 7, P7)  BRP(P5, 5, 8, P8)  BRP(P6, 6, 9, P9)
            BRL(P7, 7, 10)     BRL(P8, 8, 11)

            float P12, P13, P14;
            {
                float gg = sigf(XV(55));
                sm3(XV(12), XV(13), XV(14), o1, o2, o3);
                float a = P9 * gg;
                P12 = a * o1; P13 = a * o2; P14 = a * o3;
                tacc(T, tfs_s, 9, P9 * (1.0f - gg));
            }
            float P15, P16, P17;
            BRP(P12, 12, 15, P15) BRP(P13, 13, 16, P16) BRP(P14, 14, 17, P17)
            float P18, P19;
            BRP(P16, 16, 18, P18) BRP(P17, 17, 19, P19)
            float P20, P21;
            BRP(P18, 18, 20, P20) BRP(P19, 19, 21, P21)

            {
                float gg = sigf(XV(56));
                sm3(XV(22), XV(23), XV(24), o1, o2, o3);
                float a = P15 * gg;
                tacc(T, tfs_s, 22, a * o1);
                tacc(T, tfs_s, 23, a * o2);
                tacc(T, tfs_s, 24, a * o3);
                tacc(T, tfs_s, 15, P15 * (1.0f - gg));
            }
            float P25, P28, P31, P34, P37;
            {
                float gg = sigf(XV(57));
                sm5(XV(25), XV(28), XV(31), XV(34), XV(37), o1, o2, o3, o4, o5);
                float a = P20 * gg;
                P25 = a * o1; P28 = a * o2; P31 = a * o3; P34 = a * o4; P37 = a * o5;
                tacc(T, tfs_s, 20, P20 * (1.0f - gg));
            }
            {
                float Pc;
                BRP(P25, 25, 26, Pc) BRL(Pc, 26, 27)
                BRP(P28, 28, 29, Pc) BRL(Pc, 29, 30)
                BRP(P31, 31, 32, Pc) BRL(Pc, 32, 33)
                BRP(P34, 34, 35, Pc) BRL(Pc, 35, 36)
                BRP(P37, 37, 38, Pc) BRL(Pc, 38, 39)
            }
            float P40, P43, P46, P49, P52;
            {
                float gg = sigf(XV(58));
                sm5(XV(40), XV(43), XV(46), XV(49), XV(52), o1, o2, o3, o4, o5);
                float a = P21 * gg;
                P40 = a * o1; P43 = a * o2; P46 = a * o3; P49 = a * o4; P52 = a * o5;
                tacc(T, tfs_s, 21, P21 * (1.0f - gg));
            }
            {
                float Pc;
                BRP(P40, 40, 41, Pc) BRL(Pc, 41, 42)
                BRP(P43, 43, 44, Pc) BRL(Pc, 44, 45)
                BRP(P46, 46, 47, Pc) BRL(Pc, 47, 48)
                BRP(P49, 49, 50, Pc) BRL(Pc, 50, 51)
                BRP(P52, 52, 53, Pc) BRL(Pc, 53, 54)
            }
#undef BRP
#undef BRL
#undef XV

            float X = xyz[(size_t)pg * 3 + 0];
            float Y = xyz[(size_t)pg * 3 + 1];
            float Z = xyz[(size_t)pg * 3 + 2];
            float xb0 = T[0] * X + T[1] * Y + T[2]  * Z + T[3];
            float xb1 = T[4] * X + T[5] * Y + T[6]  * Z + T[7];
            float xb2 = T[8] * X + T[9] * Y + T[10] * Z + T[11];

            float4 qv = *(const float4*)(quats + (size_t)pg * 4);
            {
                float inv = rsqrtf(qv.x * qv.x + qv.y * qv.y + qv.z * qv.z + qv.w * qv.w);
                qv.x *= inv; qv.y *= inv; qv.z *= inv; qv.w *= inv;
            }
            float r = qv.x, xq = qv.y, yq = qv.z, zq = qv.w;
            float R[3][3];
            R[0][0] = 1.0f - 2.0f * (yq * yq + zq * zq);
            R[0][1] = 2.0f * (xq * yq - r * zq);
            R[0][2] = 2.0f * (xq * zq + r * yq);
            R[1][0] = 2.0f * (xq * yq + r * zq);
            R[1][1] = 1.0f - 2.0f * (xq * xq + zq * zq);
            R[1][2] = 2.0f * (yq * zq - r * xq);
            R[2][0] = 2.0f * (xq * zq - r * yq);
            R[2][1] = 2.0f * (yq * zq + r * xq);
            R[2][2] = 1.0f - 2.0f * (xq * xq + yq * yq);

            float rb[3][3];
            #pragma unroll
            for (int i = 0; i < 3; ++i)
                #pragma unroll
                for (int k = 0; k < 3; ++k)
                    rb[i][k] = T[i * 4 + 0] * R[0][k] + T[i * 4 + 1] * R[1][k] + T[i * 4 + 2] * R[2][k];

            float m00 = rb[0][0], m01 = rb[0][1], m02 = rb[0][2];
            float m10 = rb[1][0], m11 = rb[1][1], m12 = rb[1][2];
            float m20 = rb[2][0], m21 = rb[2][1], m22 = rb[2][2];
            float t0 = 1.0f + m00 + m11 + m22;
            float t1 = 1.0f + m00 - m11 - m22;
            float t2 = 1.0f - m00 + m11 - m22;
            float t3 = 1.0f - m00 - m11 + m22;

            int best = 0; float tb = t0;
            if (t1 > tb) { best = 1; tb = t1; }
            if (t2 > tb) { best = 2; tb = t2; }
            if (t3 > tb) { best = 3; tb = t3; }

            float qa, qb2, qc, qd;
            if (best == 0)      { qa = t0;        qb2 = m21 - m12; qc = m02 - m20; qd = m10 - m01; }
            else if (best == 1) { qa = m21 - m12; qb2 = t1;        qc = m01 + m10; qd = m02 + m20; }
            else if (best == 2) { qa = m02 - m20; qb2 = m01 + m10; qc = t2;        qd = m12 + m21; }
            else                { qa = m10 - m01; qb2 = m02 + m20; qc = m12 + m21; qd = t3;        }
            float scale = 0.5f * rsqrtf(fmaxf(tb, 1e-8f));
            qa *= scale; qb2 *= scale; qc *= scale; qd *= scale;
            float qinv = rsqrtf(qa * qa + qb2 * qb2 + qc * qc + qd * qd);
            qa *= qinv; qb2 *= qinv; qc *= qinv; qd *= qinv;

            const size_t n = (size_t)Npts;
            out[(size_t)pg * 3 + 0] = xb0;
            out[(size_t)pg * 3 + 1] = xb1;
            out[(size_t)pg * 3 + 2] = xb2;
            float* ro = out + 3 * n + (size_t)pg * 9;
            #pragma unroll
            for (int i = 0; i < 3; ++i)
                #pragma unroll
                for (int k = 0; k < 3; ++k) ro[i * 3 + k] = rb[i][k];
            float4* qo = (float4*)(out + 12 * n + (size_t)pg * 4);
            *qo = make_float4(qa, qb2, qc, qd);
            float4* to = (float4*)(out + 16 * n + (size_t)pg * 16);
            to[0] = make_float4(T[0],  T[1],  T[2],  T[3]);
            to[1] = make_float4(T[4],  T[5],  T[6],  T[7]);
            to[2] = make_float4(T[8],  T[9],  T[10], T[11]);
            to[3] = make_float4(T[12], T[13], T[14], T[15]);
        }
        __syncwarp();
    }
}

extern "C" void kernel_launch(void* const* d_in, const int* in_sizes, int n_in,
                              void* d_out, int out_size)
{
    const float* xyz      = (const float*)d_in[0];
    const float* quats    = (const float*)d_in[1];
    const float* tfs      = (const float*)d_in[2];
    const float* aabb_min = (const float*)d_in[3];
    const float* aabb_max = (const float*)d_in[4];
    const float* W0 = (const float*)d_in[5];
    const float* b0 = (const float*)d_in[6];
    const float* W1 = (const float*)d_in[7];
    const float* b1 = (const float*)d_in[8];
    const float* W2 = (const float*)d_in[9];
    const float* b2 = (const float*)d_in[10];
    const float* W3 = (const float*)d_in[11];
    const float* b3 = (const float*)d_in[12];
    float* out = (float*)d_out;

    int Npts = in_sizes[0] / 3;
    int ntiles = (Npts + TILE - 1) / TILE;

    int sms = 0;
    cudaDeviceGetAttribute(&sms, cudaDevAttrMultiProcessorCount, 0);
    if (sms <= 0) sms = 148;
    int grid = (sms < ntiles) ? sms : ntiles;

    prep_kernel<<<64, 256>>>(W1, W2, W3);

    cudaFuncSetAttribute(skin_mma_kernel,
                         cudaFuncAttributeMaxDynamicSharedMemorySize, SMEM_TOTAL);
    skin_mma_kernel<<<grid, 512, SMEM_TOTAL>>>(
        xyz, quats, tfs, aabb_min, aabb_max,
        W0, b0, b1, b2, b3, out, Npts, ntiles);
}

// round 10
// speedup vs baseline: 8.3594x; 1.0295x over previous
#include <cuda_runtime.h>
#include <cuda_fp16.h>
#include <stdint.h>

// SkinningField R10: R9 + tfs in __constant__ (LDC off the LSU port) +
// T-blend via packed fma.rn.f32x2 (880 FFMA -> 440 FFMA2, identical math).

#define H    128
#define NB   55
#define TILE 512          // 16 warps x 32 points
#define NWARP 16
#define WSTR 136
#define ESTR 61

#define OFF_W1  0
#define OFF_W2  34816
#define OFF_W3  69632
#define OFF_W0  87040
#define OFF_B0  (OFF_W0 + 1536)
#define OFF_B1  (OFF_B0 + 512)
#define OFF_B2  (OFF_B1 + 512)
#define OFF_B3  (OFF_B2 + 512)
#define OFF_TFS (OFF_B3 + 256)
#define OFF_ES  (OFF_TFS + 3520)
#define SMEM_TOTAL (OFF_ES + NWARP * 32 * ESTR * 4)   // 218816

struct __align__(16) WBlob {
    __half w1[128 * WSTR];
    __half w2[128 * WSTR];
    __half w3[64 * WSTR];
};
__device__ WBlob g_wt;

__constant__ double2 c_tfs[NB * 4];   // 55 bones x 16 floats, viewed as 4x double2

// ---------------- helpers ----------------
__device__ __forceinline__ uint32_t smem_u32(const void* p) {
    uint32_t a;
    asm("{ .reg .u64 t; cvta.to.shared.u64 t, %1; cvt.u32.u64 %0, t; }" : "=r"(a) : "l"(p));
    return a;
}
__device__ __forceinline__ float sigf(float v) {
    return __fdividef(1.0f, 1.0f + __expf(-v));
}
__device__ __forceinline__ void sm3(float a, float b, float c, float& oa, float& ob, float& oc) {
    float m = fmaxf(a, fmaxf(b, c));
    float ea = __expf(a - m), eb = __expf(b - m), ec = __expf(c - m);
    float inv = __fdividef(1.0f, ea + eb + ec);
    oa = ea * inv; ob = eb * inv; oc = ec * inv;
}
__device__ __forceinline__ void sm5(float a, float b, float c, float d, float e,
                                    float& oa, float& ob, float& oc, float& od, float& oe) {
    float m = fmaxf(fmaxf(a, b), fmaxf(fmaxf(c, d), e));
    float ea = __expf(a - m), eb = __expf(b - m), ec = __expf(c - m),
          ed = __expf(d - m), ee = __expf(e - m);
    float inv = __fdividef(1.0f, ea + eb + ec + ed + ee);
    oa = ea * inv; ob = eb * inv; oc = ec * inv; od = ed * inv; oe = ee * inv;
}
__device__ __forceinline__ uint32_t pack_h2(float h0, float h1) {
    uint32_t w;
    asm("cvt.rn.f16x2.f32 %0, %1, %2;" : "=r"(w) : "f"(h1), "f"(h0));
    return w;
}
__device__ __forceinline__ uint32_t h2exp_fast(uint32_t t) {
    uint32_t r;
    const uint32_t log2e_h2 = 0x3dc53dc5u;  // (1.4427, 1.4427) fp16x2
    asm("{ .reg .b32 s;\n\t"
        "mul.rn.f16x2 s, %1, %2;\n\t"
        "ex2.approx.f16x2 %0, s; }"
        : "=r"(r) : "r"(t), "r"(log2e_h2));
    return r;
}
__device__ __forceinline__ void sp2(float y0, float y1, float& o0, float& o1) {
    uint32_t t = pack_h2(-fabsf(y0), -fabsf(y1));
    uint32_t e = h2exp_fast(t);
    __half2 eh = *reinterpret_cast<__half2*>(&e);
    float e0 = __low2float(eh), e1 = __high2float(eh);
    o0 = fmaxf(y0, 0.0f) + __logf(1.0f + e0);
    o1 = fmaxf(y1, 0.0f) + __logf(1.0f + e1);
}

// packed f32x2 FMA: r = a*b + c  (elementwise on the two f32 halves)
__device__ __forceinline__ unsigned long long fma2(unsigned long long a,
                                                   unsigned long long b,
                                                   unsigned long long c) {
    unsigned long long r;
    asm("fma.rn.f32x2 %0, %1, %2, %3;" : "=l"(r) : "l"(a), "l"(b), "l"(c));
    return r;
}
__device__ __forceinline__ unsigned long long bcast2(float w) {
    unsigned long long r;
    asm("mov.b64 %0, {%1, %1};" : "=l"(r) : "f"(w));
    return r;
}
__device__ __forceinline__ void unpack2(unsigned long long v, float& lo, float& hi) {
    asm("mov.b64 {%0, %1}, %2;" : "=f"(lo), "=f"(hi) : "l"(v));
}

__device__ __forceinline__ void mma_f16(float& d0, float& d1, float& d2, float& d3,
                                        uint32_t a0, uint32_t a1, uint32_t a2, uint32_t a3,
                                        uint32_t b0, uint32_t b1) {
    asm volatile("mma.sync.aligned.m16n8k16.row.col.f32.f16.f16.f32 "
                 "{%0,%1,%2,%3}, {%4,%5,%6,%7}, {%8,%9}, {%0,%1,%2,%3};"
                 : "+f"(d0), "+f"(d1), "+f"(d2), "+f"(d3)
                 : "r"(a0), "r"(a1), "r"(a2), "r"(a3), "r"(b0), "r"(b1));
}

__device__ __forceinline__ void ldx4(uint32_t b[4], uint32_t base, int lane, int n0, int k0) {
    int grp = lane >> 3, r = lane & 7;
    int row = n0 + r + ((grp >> 1) << 3);
    int col = k0 + ((grp & 1) << 3);
    uint32_t addr = base + (uint32_t)(row * WSTR + col) * 2u;
    asm volatile("ldmatrix.sync.aligned.m8n8.x4.shared.b16 {%0,%1,%2,%3}, [%4];"
                 : "=r"(b[0]), "=r"(b[1]), "=r"(b[2]), "=r"(b[3]) : "r"(addr));
}

template <int NC>
__device__ __forceinline__ void gemm_layer(float acc[][4], const uint32_t ahi[8][4],
                                           uint32_t wsm, int lane) {
    #pragma unroll
    for (int j = 0; j < NC; ++j) { acc[j][0] = 0.f; acc[j][1] = 0.f; acc[j][2] = 0.f; acc[j][3] = 0.f; }
    #pragma unroll
    for (int kk = 0; kk < 8; ++kk) {
        #pragma unroll
        for (int jj = 0; jj < NC / 2; ++jj) {
            uint32_t bh[4];
            ldx4(bh, wsm, lane, 16 * jj, 16 * kk);
            float* aL = acc[2 * jj];
            float* aR = acc[2 * jj + 1];
            mma_f16(aL[0], aL[1], aL[2], aL[3], ahi[kk][0], ahi[kk][1], ahi[kk][2], ahi[kk][3], bh[0], bh[1]);
            mma_f16(aR[0], aR[1], aR[2], aR[3], ahi[kk][0], ahi[kk][1], ahi[kk][2], ahi[kk][3], bh[2], bh[3]);
        }
    }
}

__device__ __forceinline__ void act_pack(const float acc[][4], const float* bias_s,
                                         uint32_t ahi[8][4], int lane) {
    const int cbase = 2 * (lane & 3);
    #pragma unroll
    for (int j = 0; j < 16; ++j) {
        int c = 8 * j + cbase;
        float h0, h1, h2, h3;
        sp2(acc[j][0] + bias_s[c], acc[j][1] + bias_s[c + 1], h0, h1);
        sp2(acc[j][2] + bias_s[c], acc[j][3] + bias_s[c + 1], h2, h3);
        int kk = j >> 1, half = (j & 1) << 1;
        ahi[kk][half]     = pack_h2(h0, h1);
        ahi[kk][half + 1] = pack_h2(h2, h3);
    }
}

// T-blend accumulate: TP[8] packed f32x2; tfs row from constant memory
__device__ __forceinline__ void tacc(unsigned long long TP[8], int b, float w) {
    unsigned long long wpk = bcast2(w);
    #pragma unroll
    for (int i = 0; i < 4; ++i) {
        double2 v = c_tfs[b * 4 + i];
        TP[2 * i]     = fma2(wpk, *(unsigned long long*)&v.x, TP[2 * i]);
        TP[2 * i + 1] = fma2(wpk, *(unsigned long long*)&v.y, TP[2 * i + 1]);
    }
}

// ---------------- prep ----------------
__global__ void prep_kernel(const float* __restrict__ W1, const float* __restrict__ W2,
                            const float* __restrict__ W3) {
    int tid = blockIdx.x * blockDim.x + threadIdx.x;
    int stride = gridDim.x * blockDim.x;
    for (int o = tid; o < 128 * WSTR; o += stride) {
        int n = o / WSTR, k = o % WSTR;
        float f1 = 0.f, f2 = 0.f;
        if (k < 128) { f1 = W1[k * 128 + n]; f2 = W2[k * 128 + n]; }
        g_wt.w1[o] = __float2half_rn(f1);
        g_wt.w2[o] = __float2half_rn(f2);
    }
    for (int o = tid; o < 64 * WSTR; o += stride) {
        int n = o / WSTR, k = o % WSTR;
        float f = (n < 59 && k < 128) ? W3[k * 59 + n] : 0.f;
        g_wt.w3[o] = __float2half_rn(f);
    }
}

// ---------------- main kernel ----------------
__global__ void __launch_bounds__(512, 1)
skin_mma_kernel(const float* __restrict__ xyz,  const float* __restrict__ quats,
                const float* __restrict__ tfs,  const float* __restrict__ aabb_min,
                const float* __restrict__ aabb_max,
                const float* __restrict__ W0, const float* __restrict__ b0,
                const float* __restrict__ b1, const float* __restrict__ b2,
                const float* __restrict__ b3,
                float* __restrict__ out, int Npts, int ntiles)
{
    extern __shared__ char smem[];
    const int tid  = threadIdx.x;
    const int wid  = tid >> 5;
    const int lane = tid & 31;

    {
        const uint4* src = (const uint4*)&g_wt;
        uint4* dst = (uint4*)smem;
        for (int i = tid; i < (int)(sizeof(WBlob) / 16); i += 512) dst[i] = src[i];
    }
    float* w0s  = (float*)(smem + OFF_W0);
    float* b0s  = (float*)(smem + OFF_B0);
    float* b1s  = (float*)(smem + OFF_B1);
    float* b2s  = (float*)(smem + OFF_B2);
    float* b3s  = (float*)(smem + OFF_B3);
    for (int i = tid; i < 3 * H; i += 512) w0s[i] = W0[i];
    if (tid < H) { b0s[tid] = b0[tid]; b1s[tid] = b1[tid]; b2s[tid] = b2[tid]; }
    if (tid < 64) b3s[tid] = (tid < 59) ? b3[tid] : 0.0f;
    __syncthreads();

    const uint32_t u_w1 = smem_u32(smem + OFF_W1);
    const uint32_t u_w2 = smem_u32(smem + OFF_W2);
    const uint32_t u_w3 = smem_u32(smem + OFF_W3);
    float* es_w = (float*)(smem + OFF_ES) + wid * (32 * ESTR);

    const float amn0 = __ldg(aabb_min + 0), amn1 = __ldg(aabb_min + 1), amn2 = __ldg(aabb_min + 2);
    const float amx0 = __ldg(aabb_max + 0), amx1 = __ldg(aabb_max + 1), amx2 = __ldg(aabb_max + 2);
    const float sc0 = 2.0f / (amx0 - amn0), sc1 = 2.0f / (amx1 - amn1), sc2 = 2.0f / (amx2 - amn2);

    const int g = lane >> 2;
    const int cbase = 2 * (lane & 3);
    const int wpar = wid & 1;

    for (int t = blockIdx.x; t < ntiles; t += gridDim.x) {
        const int pbase_w = t * TILE + wid * 32;

        #pragma unroll
        for (int hh = 0; hh < 2; ++hh) {
            const int hf = hh ^ wpar;
            const int base16 = pbase_w + hf * 16;
            uint32_t ahi[8][4];
            float acc[16][4];

            {
                int pA = base16 + g;     if (pA >= Npts) pA = Npts - 1;
                int pB = base16 + g + 8; if (pB >= Npts) pB = Npts - 1;
                float xA0 = (xyz[(size_t)pA * 3 + 0] - amn0) * sc0 - 1.0f;
                float xA1 = (xyz[(size_t)pA * 3 + 1] - amn1) * sc1 - 1.0f;
                float xA2 = (xyz[(size_t)pA * 3 + 2] - amn2) * sc2 - 1.0f;
                float xB0 = (xyz[(size_t)pB * 3 + 0] - amn0) * sc0 - 1.0f;
                float xB1 = (xyz[(size_t)pB * 3 + 1] - amn1) * sc1 - 1.0f;
                float xB2 = (xyz[(size_t)pB * 3 + 2] - amn2) * sc2 - 1.0f;
                #pragma unroll
                for (int j = 0; j < 16; ++j) {
                    int c = 8 * j + cbase;
                    float w0c = w0s[c],     w1c = w0s[128 + c],     w2c = w0s[256 + c];
                    float w0d = w0s[c + 1], w1d = w0s[128 + c + 1], w2d = w0s[256 + c + 1];
                    float y0 = b0s[c]     + xA0 * w0c + xA1 * w1c + xA2 * w2c;
                    float y1 = b0s[c + 1] + xA0 * w0d + xA1 * w1d + xA2 * w2d;
                    float y2 = b0s[c]     + xB0 * w0c + xB1 * w1c + xB2 * w2c;
                    float y3 = b0s[c + 1] + xB0 * w0d + xB1 * w1d + xB2 * w2d;
                    float h0, h1, h2, h3;
                    sp2(y0, y1, h0, h1);
                    sp2(y2, y3, h2, h3);
                    int kk = j >> 1, half = (j & 1) << 1;
                    ahi[kk][half]     = pack_h2(h0, h1);
                    ahi[kk][half + 1] = pack_h2(h2, h3);
                }
            }

            gemm_layer<16>(acc, ahi, u_w1, lane);
            act_pack(acc, b1s, ahi, lane);
            gemm_layer<16>(acc, ahi, u_w2, lane);
            act_pack(acc, b2s, ahi, lane);
            gemm_layer<8>(acc, ahi, u_w3, lane);

            __syncwarp();
            #pragma unroll
            for (int j = 0; j < 8; ++j) {
                int c = 8 * j + cbase;
                int r0 = hf * 16 + g, r1 = r0 + 8;
                if (c < 59) {
                    es_w[r0 * ESTR + c] = acc[j][0] + b3s[c];
                    es_w[r1 * ESTR + c] = acc[j][2] + b3s[c];
                }
                if (c + 1 < 59) {
                    es_w[r0 * ESTR + c + 1] = acc[j][1] + b3s[c + 1];
                    es_w[r1 * ESTR + c + 1] = acc[j][3] + b3s[c + 1];
                }
            }
            __syncwarp();
        }

        // ---- epilogue: all 32 lanes; T blended in packed f32x2 from constant ----
        const int pg = pbase_w + lane;
        if (pg < Npts) {
            const float* xr = es_w + lane * ESTR;
#define XV(i) xr[i]
            unsigned long long TP[8];
            #pragma unroll
            for (int q = 0; q < 8; ++q) TP[q] = 0ull;

            float o1, o2, o3, o4, o5;
            float s0 = sigf(XV(0));
            sm3(XV(1), XV(2), XV(3), o1, o2, o3);
            float P1 = s0 * o1, P2 = s0 * o2, P3 = s0 * o3;
            tacc(TP, 0, 1.0f - s0);

#define BRP(Pp, pidx, cidx, Pc) { float s_ = sigf(XV(cidx)); Pc = Pp * s_; \
                                  tacc(TP, pidx, Pp * (1.0f - s_)); }
#define BRL(Pp, pidx, cidx)     { float s_ = sigf(XV(cidx)); \
                                  tacc(TP, cidx, Pp * s_); \
                                  tacc(TP, pidx, Pp * (1.0f - s_)); }

            float P4, P5, P6;
            BRP(P1, 1, 4, P4)  BRP(P2, 2, 5, P5)  BRP(P3, 3, 6, P6)
            float P7, P8, P9;
            BRP(P4, 4, 7, P7)  BRP(P5, 5, 8, P8)  BRP(P6, 6, 9, P9)
            BRL(P7, 7, 10)     BRL(P8, 8, 11)

            float P12, P13, P14;
            {
                float gg = sigf(XV(55));
                sm3(XV(12), XV(13), XV(14), o1, o2, o3);
                float a = P9 * gg;
                P12 = a * o1; P13 = a * o2; P14 = a * o3;
                tacc(TP, 9, P9 * (1.0f - gg));
            }
            float P15, P16, P17;
            BRP(P12, 12, 15, P15) BRP(P13, 13, 16, P16) BRP(P14, 14, 17, P17)
            float P18, P19;
            BRP(P16, 16, 18, P18) BRP(P17, 17, 19, P19)
            float P20, P21;
            BRP(P18, 18, 20, P20) BRP(P19, 19, 21, P21)

            {
                float gg = sigf(XV(56));
                sm3(XV(22), XV(23), XV(24), o1, o2, o3);
                float a = P15 * gg;
                tacc(TP, 22, a * o1);
                tacc(TP, 23, a * o2);
                tacc(TP, 24, a * o3);
                tacc(TP, 15, P15 * (1.0f - gg));
            }
            float P25, P28, P31, P34, P37;
            {
                float gg = sigf(XV(57));
                sm5(XV(25), XV(28), XV(31), XV(34), XV(37), o1, o2, o3, o4, o5);
                float a = P20 * gg;
                P25 = a * o1; P28 = a * o2; P31 = a * o3; P34 = a * o4; P37 = a * o5;
                tacc(TP, 20, P20 * (1.0f - gg));
            }
            {
                float Pc;
                BRP(P25, 25, 26, Pc) BRL(Pc, 26, 27)
                BRP(P28, 28, 29, Pc) BRL(Pc, 29, 30)
                BRP(P31, 31, 32, Pc) BRL(Pc, 32, 33)
                BRP(P34, 34, 35, Pc) BRL(Pc, 35, 36)
                BRP(P37, 37, 38, Pc) BRL(Pc, 38, 39)
            }
            float P40, P43, P46, P49, P52;
            {
                float gg = sigf(XV(58));
                sm5(XV(40), XV(43), XV(46), XV(49), XV(52), o1, o2, o3, o4, o5);
                float a = P21 * gg;
                P40 = a * o1; P43 = a * o2; P46 = a * o3; P49 = a * o4; P52 = a * o5;
                tacc(TP, 21, P21 * (1.0f - gg));
            }
            {
                float Pc;
                BRP(P40, 40, 41, Pc) BRL(Pc, 41, 42)
                BRP(P43, 43, 44, Pc) BRL(Pc, 44, 45)
                BRP(P46, 46, 47, Pc) BRL(Pc, 47, 48)
                BRP(P49, 49, 50, Pc) BRL(Pc, 50, 51)
                BRP(P52, 52, 53, Pc) BRL(Pc, 53, 54)
            }
#undef BRP
#undef BRL
#undef XV

            // unpack T
            float T[16];
            #pragma unroll
            for (int q = 0; q < 8; ++q) unpack2(TP[q], T[2 * q], T[2 * q + 1]);

            float X = xyz[(size_t)pg * 3 + 0];
            float Y = xyz[(size_t)pg * 3 + 1];
            float Z = xyz[(size_t)pg * 3 + 2];
            float xb0 = T[0] * X + T[1] * Y + T[2]  * Z + T[3];
            float xb1 = T[4] * X + T[5] * Y + T[6]  * Z + T[7];
            float xb2 = T[8] * X + T[9] * Y + T[10] * Z + T[11];

            float4 qv = *(const float4*)(quats + (size_t)pg * 4);
            {
                float inv = rsqrtf(qv.x * qv.x + qv.y * qv.y + qv.z * qv.z + qv.w * qv.w);
                qv.x *= inv; qv.y *= inv; qv.z *= inv; qv.w *= inv;
            }
            float r = qv.x, xq = qv.y, yq = qv.z, zq = qv.w;
            float R[3][3];
            R[0][0] = 1.0f - 2.0f * (yq * yq + zq * zq);
            R[0][1] = 2.0f * (xq * yq - r * zq);
            R[0][2] = 2.0f * (xq * zq + r * yq);
            R[1][0] = 2.0f * (xq * yq + r * zq);
            R[1][1] = 1.0f - 2.0f * (xq * xq + zq * zq);
            R[1][2] = 2.0f * (yq * zq - r * xq);
            R[2][0] = 2.0f * (xq * zq - r * yq);
            R[2][1] = 2.0f * (yq * zq + r * xq);
            R[2][2] = 1.0f - 2.0f * (xq * xq + yq * yq);

            float rb[3][3];
            #pragma unroll
            for (int i = 0; i < 3; ++i)
                #pragma unroll
                for (int k = 0; k < 3; ++k)
                    rb[i][k] = T[i * 4 + 0] * R[0][k] + T[i * 4 + 1] * R[1][k] + T[i * 4 + 2] * R[2][k];

            float m00 = rb[0][0], m01 = rb[0][1], m02 = rb[0][2];
            float m10 = rb[1][0], m11 = rb[1][1], m12 = rb[1][2];
            float m20 = rb[2][0], m21 = rb[2][1], m22 = rb[2][2];
            float t0 = 1.0f + m00 + m11 + m22;
            float t1 = 1.0f + m00 - m11 - m22;
            float t2 = 1.0f - m00 + m11 - m22;
            float t3 = 1.0f - m00 - m11 + m22;

            int best = 0; float tb = t0;
            if (t1 > tb) { best = 1; tb = t1; }
            if (t2 > tb) { best = 2; tb = t2; }
            if (t3 > tb) { best = 3; tb = t3; }

            float qa, qb2, qc, qd;
            if (best == 0)      { qa = t0;        qb2 = m21 - m12; qc = m02 - m20; qd = m10 - m01; }
            else if (best == 1) { qa = m21 - m12; qb2 = t1;        qc = m01 + m10; qd = m02 + m20; }
            else if (best == 2) { qa = m02 - m20; qb2 = m01 + m10; qc = t2;        qd = m12 + m21; }
            else                { qa = m10 - m01; qb2 = m02 + m20; qc = m12 + m21; qd = t3;        }
            float scale = 0.5f * rsqrtf(fmaxf(tb, 1e-8f));
            qa *= scale; qb2 *= scale; qc *= scale; qd *= scale;
            float qinv = rsqrtf(qa * qa + qb2 * qb2 + qc * qc + qd * qd);
            qa *= qinv; qb2 *= qinv; qc *= qinv; qd *= qinv;

            const size_t n = (size_t)Npts;
            out[(size_t)pg * 3 + 0] = xb0;
            out[(size_t)pg * 3 + 1] = xb1;
            out[(size_t)pg * 3 + 2] = xb2;
            float* ro = out + 3 * n + (size_t)pg * 9;
            #pragma unroll
            for (int i = 0; i < 3; ++i)
                #pragma unroll
                for (int k = 0; k < 3; ++k) ro[i * 3 + k] = rb[i][k];
            float4* qo = (float4*)(out + 12 * n + (size_t)pg * 4);
            *qo = make_float4(qa, qb2, qc, qd);
            float4* to = (float4*)(out + 16 * n + (size_t)pg * 16);
            to[0] = make_float4(T[0],  T[1],  T[2],  T[3]);
            to[1] = make_float4(T[4],  T[5],  T[6],  T[7]);
            to[2] = make_float4(T[8],  T[9],  T[10], T[11]);
            to[3] = make_float4(T[12], T[13], T[14], T[15]);
        }
        __syncwarp();
    }
}

extern "C" void kernel_launch(void* const* d_in, const int* in_sizes, int n_in,
                              void* d_out, int out_size)
{
    const float* xyz      = (const float*)d_in[0];
    const float* quats    = (const float*)d_in[1];
    const float* tfs      = (const float*)d_in[2];
    const float* aabb_min = (const float*)d_in[3];
    const float* aabb_max = (const float*)d_in[4];
    const float* W0 = (const float*)d_in[5];
    const float* b0 = (const float*)d_in[6];
    const float* W1 = (const float*)d_in[7];
    const float* b1 = (const float*)d_in[8];
    const float* W2 = (const float*)d_in[9];
    const float* b2 = (const float*)d_in[10];
    const float* W3 = (const float*)d_in[11];
    const float* b3 = (const float*)d_in[12];
    float* out = (float*)d_out;

    int Npts = in_sizes[0] / 3;
    int ntiles = (Npts + TILE - 1) / TILE;

    int sms = 0;
    cudaDeviceGetAttribute(&sms, cudaDevAttrMultiProcessorCount, 0);
    if (sms <= 0) sms = 148;
    int grid = (sms < ntiles) ? sms : ntiles;

    // tfs -> constant memory (D2D async, graph-capturable)
    cudaMemcpyToSymbolAsync(c_tfs, tfs, NB * 16 * sizeof(float), 0,
                            cudaMemcpyDeviceToDevice);

    prep_kernel<<<64, 256>>>(W1, W2, W3);

    cudaFuncSetAttribute(skin_mma_kernel,
                         cudaFuncAttributeMaxDynamicSharedMemorySize, SMEM_TOTAL);
    skin_mma_kernel<<<grid, 512, SMEM_TOTAL>>>(
        xyz, quats, tfs, aabb_min, aabb_max,
        W0, b0, b1, b2, b3, out, Npts, ntiles);
}